// round 1
// baseline (speedup 1.0000x reference)
#include <cuda_runtime.h>
#include <cuda_bf16.h>
#include <math.h>

// ---------------- problem constants ----------------
#define BB   32
#define LL   512
#define DDIM 192
#define DEPTH 12
#define HH   6
#define DHH  32
#define KCLIP 32
#define BINS 65
#define NROW (BB*LL)          // 16384
#define QKVN (3*DDIM)         // 576
#define FFN  (4*DDIM)         // 768

// ---------------- scratch (static device arrays; no allocation) ----------------
__device__ float g_x  [NROW*DDIM];
__device__ float g_h  [NROW*DDIM];
__device__ float g_qkv[NROW*QKVN];
__device__ float g_o  [NROW*DDIM];
__device__ float g_ff [NROW*FFN];
__device__ float g_maskf[NROW];
__device__ int   g_mask_is_u8;

// ---------------- mask dtype detection ----------------
__global__ void mask_reset_kernel() { g_mask_is_u8 = 0; }

__global__ void mask_detect_kernel(const unsigned char* __restrict__ m) {
    int i = blockIdx.x * 256 + threadIdx.x;
    if (i < NROW && (i & 3) != 0 && m[i] != 0) atomicOr(&g_mask_is_u8, 1);
}

__global__ void mask_expand_kernel(const void* __restrict__ m) {
    int i = blockIdx.x * 256 + threadIdx.x;
    if (i >= NROW) return;
    int v;
    if (g_mask_is_u8) v = ((const unsigned char*)m)[i];
    else              v = ((const int*)m)[i];
    g_maskf[i] = v ? 1.0f : 0.0f;
}

// ---------------- embedding ----------------
__global__ void embed_kernel(const int* __restrict__ seq,
                             const float* __restrict__ emb,
                             float* __restrict__ x) {
    int i = blockIdx.x * 256 + threadIdx.x;   // over NROW*DDIM
    if (i >= NROW * DDIM) return;
    int row = i / DDIM, c = i - row * DDIM;
    x[i] = emb[seq[row] * DDIM + c];
}

// ---------------- layernorm (warp per row) ----------------
__global__ void ln_kernel(const float* __restrict__ x,
                          const float* __restrict__ s,
                          const float* __restrict__ b,
                          float* __restrict__ out) {
    int row  = blockIdx.x * 8 + (threadIdx.x >> 5);
    int lane = threadIdx.x & 31;
    const float* xr = x + (size_t)row * DDIM;
    float v[6], sum = 0.f;
#pragma unroll
    for (int j = 0; j < 6; j++) { v[j] = xr[lane + 32*j]; sum += v[j]; }
#pragma unroll
    for (int o = 16; o; o >>= 1) sum += __shfl_xor_sync(0xffffffffu, sum, o);
    float mu = sum * (1.0f / DDIM);
    float vs = 0.f;
#pragma unroll
    for (int j = 0; j < 6; j++) { float d = v[j] - mu; vs += d * d; }
#pragma unroll
    for (int o = 16; o; o >>= 1) vs += __shfl_xor_sync(0xffffffffu, vs, o);
    float inv = rsqrtf(vs * (1.0f / DDIM) + 1e-5f);
    float* orow = out + (size_t)row * DDIM;
#pragma unroll
    for (int j = 0; j < 6; j++) {
        int c = lane + 32*j;
        orow[c] = (v[j] - mu) * inv * s[c] + b[c];
    }
}

// ---------------- tiled SGEMM: C[M,N] = A[M,K] @ W[N,K]^T (+bias, epilogue) ----------
// MODE 0: C = acc + bias
// MODE 1: C = res + acc + bias        (residual add)
// MODE 2: C = gelu(acc + bias)        (exact gelu)
template <int MODE>
__global__ __launch_bounds__(256, 4)
void sgemm_kernel(const float* __restrict__ A, const float* __restrict__ W,
                  const float* __restrict__ bias, const float* __restrict__ res,
                  float* __restrict__ C, int M, int N, int K) {
    __shared__ float As[16][129];
    __shared__ float Bs[16][65];
    int tid = threadIdx.x;
    int tx = tid & 15, ty = tid >> 4;
    int m0 = blockIdx.y * 128, n0 = blockIdx.x * 64;

    float acc[8][4];
#pragma unroll
    for (int i = 0; i < 8; i++)
#pragma unroll
        for (int j = 0; j < 4; j++) acc[i][j] = 0.f;

    for (int k0 = 0; k0 < K; k0 += 16) {
#pragma unroll
        for (int j = 0; j < 8; j++) {
            int idx = j * 256 + tid;
            int r = idx >> 4, c = idx & 15;
            As[c][r] = A[(size_t)(m0 + r) * K + k0 + c];
        }
#pragma unroll
        for (int j = 0; j < 4; j++) {
            int idx = j * 256 + tid;
            int r = idx >> 4, c = idx & 15;
            Bs[c][r] = W[(size_t)(n0 + r) * K + k0 + c];
        }
        __syncthreads();
#pragma unroll
        for (int kk = 0; kk < 16; kk++) {
            float a[8], b[4];
#pragma unroll
            for (int i = 0; i < 8; i++) a[i] = As[kk][ty*8 + i];
#pragma unroll
            for (int j = 0; j < 4; j++) b[j] = Bs[kk][tx*4 + j];
#pragma unroll
            for (int i = 0; i < 8; i++)
#pragma unroll
                for (int j = 0; j < 4; j++) acc[i][j] += a[i] * b[j];
        }
        __syncthreads();
    }

#pragma unroll
    for (int i = 0; i < 8; i++) {
        int m = m0 + ty*8 + i;
#pragma unroll
        for (int j = 0; j < 4; j++) {
            int n = n0 + tx*4 + j;
            float v = acc[i][j] + bias[n];
            if (MODE == 1) v += res[(size_t)m * N + n];
            if (MODE == 2) v = 0.5f * v * (1.0f + erff(v * 0.7071067811865476f));
            C[(size_t)m * N + n] = v;
        }
    }
}

// ---------------- attention: block = (q-tile of 16, head, batch) ----------------
__global__ __launch_bounds__(256)
void attn_kernel(const float* __restrict__ qkv, const float* __restrict__ bppm,
                 const float* __restrict__ pair_w, const float* __restrict__ pair_b,
                 const float* __restrict__ relpos_w, const float* __restrict__ relpos_b,
                 float* __restrict__ o) {
    int qt = blockIdx.x;   // 0..31
    int h  = blockIdx.y;   // 0..5
    int b  = blockIdx.z;   // 0..31

    __shared__ float Qs[16][32];
    __shared__ float S[16][513];
    __shared__ float rel[BINS];
    __shared__ float red[16][16];
    __shared__ float rowmax[16], rowsum[16];
    __shared__ float msk[512];

    int tid = threadIdx.x;
    int qr = tid >> 4, kt = tid & 15;
    int q = qt * 16 + qr;

    // load Q tile (16x32)
#pragma unroll
    for (int j = 0; j < 2; j++) {
        int id = tid + j * 256;
        int r = id >> 5, d = id & 31;
        Qs[r][d] = qkv[((size_t)(b * LL + qt * 16 + r)) * QKVN + h * DHH + d];
    }
    if (tid < BINS) rel[tid] = relpos_w[h * BINS + tid];
    for (int k = tid; k < 512; k += 256) msk[k] = g_maskf[b * LL + k];
    __syncthreads();

    float pw   = pair_w[h];
    float addc = pair_b[h] + relpos_b[h];
    const float scale = 0.17677669529663687f;  // 1/sqrt(32)

    // phase 2: scores
    for (int k = kt; k < 512; k += 16) {
        const float4* K4 = reinterpret_cast<const float4*>(
            qkv + ((size_t)(b * LL + k)) * QKVN + DDIM + h * DHH);
        float dot = 0.f;
#pragma unroll
        for (int d4 = 0; d4 < 8; d4++) {
            float4 kv = K4[d4];
            dot += Qs[qr][d4*4+0]*kv.x + Qs[qr][d4*4+1]*kv.y
                 + Qs[qr][d4*4+2]*kv.z + Qs[qr][d4*4+3]*kv.w;
        }
        int diff = q - k;
        diff = max(-KCLIP, min(KCLIP, diff));
        float sv = dot * scale
                 + bppm[((size_t)b * LL + q) * LL + k] * pw
                 + addc + rel[diff + KCLIP];
        if (msk[k] == 0.f) sv = -1e9f;
        S[qr][k] = sv;
    }
    __syncthreads();

    // phase 3: softmax (two-pass over smem row)
    float lmax = -1e30f;
    for (int k = kt; k < 512; k += 16) lmax = fmaxf(lmax, S[qr][k]);
    red[qr][kt] = lmax;
    __syncthreads();
    if (tid < 16) {
        float m = red[tid][0];
#pragma unroll
        for (int j = 1; j < 16; j++) m = fmaxf(m, red[tid][j]);
        rowmax[tid] = m;
    }
    __syncthreads();
    float rm = rowmax[qr];
    float lsum = 0.f;
    for (int k = kt; k < 512; k += 16) {
        float e = __expf(S[qr][k] - rm);
        S[qr][k] = e;
        lsum += e;
    }
    red[qr][kt] = lsum;
    __syncthreads();
    if (tid < 16) {
        float s2 = 0.f;
#pragma unroll
        for (int j = 0; j < 16; j++) s2 += red[tid][j];
        rowsum[tid] = s2;
    }
    __syncthreads();

    // phase 4: O = attn @ V ; thread handles (qr, d=kt and d=kt+16)
    float inv = 1.0f / rowsum[qr];
    float acc0 = 0.f, acc1 = 0.f;
    const float* Vbase = qkv + (size_t)(b * LL) * QKVN + 2 * DDIM + h * DHH;
#pragma unroll 4
    for (int k = 0; k < 512; k++) {
        float s = S[qr][k];
        const float* Vr = Vbase + (size_t)k * QKVN;
        acc0 += s * Vr[kt];
        acc1 += s * Vr[kt + 16];
    }
    size_t orow = ((size_t)(b * LL + q)) * DDIM + h * DHH;
    o[orow + kt]      = acc0 * inv;
    o[orow + kt + 16] = acc1 * inv;
}

// ---------------- final projection: warp per row, 2 outputs ----------------
__global__ void proj_kernel(const float* __restrict__ x,
                            const float* __restrict__ pw,
                            const float* __restrict__ pb,
                            float* __restrict__ out) {
    int row  = blockIdx.x * 8 + (threadIdx.x >> 5);
    int lane = threadIdx.x & 31;
    const float* xr = x + (size_t)row * DDIM;
    float d0 = 0.f, d1 = 0.f;
#pragma unroll
    for (int j = 0; j < 6; j++) {
        int c = lane + 32*j;
        float v = xr[c];
        d0 += v * pw[c];
        d1 += v * pw[DDIM + c];
    }
#pragma unroll
    for (int o = 16; o; o >>= 1) {
        d0 += __shfl_xor_sync(0xffffffffu, d0, o);
        d1 += __shfl_xor_sync(0xffffffffu, d1, o);
    }
    if (lane == 0) {
        out[row*2 + 0] = d0 + pb[0];
        out[row*2 + 1] = d1 + pb[1];
    }
}

// ---------------- launch ----------------
extern "C" void kernel_launch(void* const* d_in, const int* in_sizes, int n_in,
                              void* d_out, int out_size) {
    const int*   seq      = (const int*)  d_in[0];
    const void*  mask     =               d_in[1];
    const float* bppm     = (const float*)d_in[2];
    const float* emb      = (const float*)d_in[3];
    const float* pair_w   = (const float*)d_in[4];
    const float* pair_b   = (const float*)d_in[5];
    const float* relpos_w = (const float*)d_in[6];
    const float* relpos_b = (const float*)d_in[7];
    const float* ln1_s    = (const float*)d_in[8];
    const float* ln1_b    = (const float*)d_in[9];
    const float* qkv_w    = (const float*)d_in[10];
    const float* qkv_b    = (const float*)d_in[11];
    const float* out_w    = (const float*)d_in[12];
    const float* out_b    = (const float*)d_in[13];
    const float* ln2_s    = (const float*)d_in[14];
    const float* ln2_b    = (const float*)d_in[15];
    const float* ff1_w    = (const float*)d_in[16];
    const float* ff1_b    = (const float*)d_in[17];
    const float* ff2_w    = (const float*)d_in[18];
    const float* ff2_b    = (const float*)d_in[19];
    const float* proj_w   = (const float*)d_in[20];
    const float* proj_b   = (const float*)d_in[21];
    float* out = (float*)d_out;

    float *x, *h, *qkvB, *o, *ff;
    cudaGetSymbolAddress((void**)&x,    g_x);
    cudaGetSymbolAddress((void**)&h,    g_h);
    cudaGetSymbolAddress((void**)&qkvB, g_qkv);
    cudaGetSymbolAddress((void**)&o,    g_o);
    cudaGetSymbolAddress((void**)&ff,   g_ff);

    // mask dtype detection + expansion (deterministic)
    mask_reset_kernel<<<1, 1>>>();
    mask_detect_kernel<<<(NROW + 255) / 256, 256>>>((const unsigned char*)mask);
    mask_expand_kernel<<<(NROW + 255) / 256, 256>>>(mask);

    // embedding
    embed_kernel<<<(NROW * DDIM) / 256, 256>>>(seq, emb, x);

    dim3 gQKV(QKVN / 64, NROW / 128);   // 9 x 128
    dim3 gOUT(DDIM / 64, NROW / 128);   // 3 x 128
    dim3 gFF1(FFN  / 64, NROW / 128);   // 12 x 128
    dim3 gATT(LL / 16, HH, BB);         // 32 x 6 x 32

    for (int i = 0; i < DEPTH; i++) {
        // h = LN1(x)
        ln_kernel<<<NROW / 8, 256>>>(x, ln1_s + i*DDIM, ln1_b + i*DDIM, h);
        // qkv = h @ qkv_w^T + qkv_b
        sgemm_kernel<0><<<gQKV, 256>>>(h, qkv_w + (size_t)i*QKVN*DDIM,
                                       qkv_b + i*QKVN, nullptr, qkvB,
                                       NROW, QKVN, DDIM);
        // attention -> o
        attn_kernel<<<gATT, 256>>>(qkvB, bppm, pair_w, pair_b,
                                   relpos_w, relpos_b, o);
        // x = x + o @ out_w^T + out_b
        sgemm_kernel<1><<<gOUT, 256>>>(o, out_w + (size_t)i*DDIM*DDIM,
                                       out_b + i*DDIM, x, x,
                                       NROW, DDIM, DDIM);
        // h = LN2(x)
        ln_kernel<<<NROW / 8, 256>>>(x, ln2_s + i*DDIM, ln2_b + i*DDIM, h);
        // ff = gelu(h @ ff1_w^T + ff1_b)
        sgemm_kernel<2><<<gFF1, 256>>>(h, ff1_w + (size_t)i*FFN*DDIM,
                                       ff1_b + i*FFN, nullptr, ff,
                                       NROW, FFN, DDIM);
        // x = x + ff @ ff2_w^T + ff2_b
        sgemm_kernel<1><<<gOUT, 256>>>(ff, ff2_w + (size_t)i*DDIM*FFN,
                                       ff2_b + i*DDIM, x, x,
                                       NROW, DDIM, FFN);
    }

    // out = x @ proj_w^T + proj_b
    proj_kernel<<<NROW / 8, 256>>>(x, proj_w, proj_b, out);
}

// round 2
// speedup vs baseline: 1.1123x; 1.1123x over previous
#include <cuda_runtime.h>
#include <cuda_bf16.h>
#include <math.h>

// ---------------- problem constants ----------------
#define BB   32
#define LL   512
#define DDIM 192
#define DEPTH 12
#define HH   6
#define DHH  32
#define KCLIP 32
#define BINS 65
#define NROW (BB*LL)          // 16384
#define QKVN (3*DDIM)         // 576
#define FFN  (4*DDIM)         // 768

// ---------------- scratch (static device arrays; no allocation) ----------------
__device__ float g_x  [NROW*DDIM];
__device__ float g_h  [NROW*DDIM];
__device__ float g_qkv[NROW*QKVN];
__device__ float g_o  [NROW*DDIM];
__device__ float g_ff [NROW*FFN];
__device__ float g_maskf[NROW];
__device__ int   g_mask_is_u8;

// ---------------- mask dtype detection ----------------
__global__ void mask_reset_kernel() { g_mask_is_u8 = 0; }

__global__ void mask_detect_kernel(const unsigned char* __restrict__ m) {
    int i = blockIdx.x * 256 + threadIdx.x;
    if (i < NROW && (i & 3) != 0 && m[i] != 0) atomicOr(&g_mask_is_u8, 1);
}

__global__ void mask_expand_kernel(const void* __restrict__ m) {
    int i = blockIdx.x * 256 + threadIdx.x;
    if (i >= NROW) return;
    int v;
    if (g_mask_is_u8) v = ((const unsigned char*)m)[i];
    else              v = ((const int*)m)[i];
    g_maskf[i] = v ? 1.0f : 0.0f;
}

// ---------------- embedding ----------------
__global__ void embed_kernel(const int* __restrict__ seq,
                             const float* __restrict__ emb,
                             float* __restrict__ x) {
    int i = blockIdx.x * 256 + threadIdx.x;   // over NROW*DDIM
    if (i >= NROW * DDIM) return;
    int row = i / DDIM, c = i - row * DDIM;
    x[i] = emb[seq[row] * DDIM + c];
}

// ---------------- layernorm (warp per row) ----------------
__global__ void ln_kernel(const float* __restrict__ x,
                          const float* __restrict__ s,
                          const float* __restrict__ b,
                          float* __restrict__ out) {
    int row  = blockIdx.x * 8 + (threadIdx.x >> 5);
    int lane = threadIdx.x & 31;
    const float* xr = x + (size_t)row * DDIM;
    float v[6], sum = 0.f;
#pragma unroll
    for (int j = 0; j < 6; j++) { v[j] = xr[lane + 32*j]; sum += v[j]; }
#pragma unroll
    for (int o = 16; o; o >>= 1) sum += __shfl_xor_sync(0xffffffffu, sum, o);
    float mu = sum * (1.0f / DDIM);
    float vs = 0.f;
#pragma unroll
    for (int j = 0; j < 6; j++) { float d = v[j] - mu; vs += d * d; }
#pragma unroll
    for (int o = 16; o; o >>= 1) vs += __shfl_xor_sync(0xffffffffu, vs, o);
    float inv = rsqrtf(vs * (1.0f / DDIM) + 1e-5f);
    float* orow = out + (size_t)row * DDIM;
#pragma unroll
    for (int j = 0; j < 6; j++) {
        int c = lane + 32*j;
        orow[c] = (v[j] - mu) * inv * s[c] + b[c];
    }
}

// ---------------- tf32 helpers ----------------
__device__ __forceinline__ unsigned tf32_of(float x) {
    unsigned u;
    asm("cvt.rna.tf32.f32 %0, %1;" : "=r"(u) : "f"(x));
    return u;
}

__device__ __forceinline__ void mma_tf32(float* c,
                                         unsigned a0, unsigned a1, unsigned a2, unsigned a3,
                                         unsigned b0, unsigned b1) {
    asm("mma.sync.aligned.m16n8k8.row.col.f32.tf32.tf32.f32 "
        "{%0,%1,%2,%3},{%4,%5,%6,%7},{%8,%9},{%0,%1,%2,%3};"
        : "+f"(c[0]), "+f"(c[1]), "+f"(c[2]), "+f"(c[3])
        : "r"(a0), "r"(a1), "r"(a2), "r"(a3), "r"(b0), "r"(b1));
}

// ---------------- TF32 tensor-core GEMM: C[M,N] = A[M,K] @ W[N,K]^T --------------
// 2-term tf32 split (3 mma passes) -> ~fp32 accuracy.
// MODE 0: C = acc + bias
// MODE 1: C = res + acc + bias        (residual add)
// MODE 2: C = gelu(acc + bias)        (exact gelu)
// BM=128, BN=64, BK=16; 8 warps in 4(m) x 2(n); warp tile 32x32.
#define AS_STRIDE 136   // 136 % 32 == 8 -> conflict-free frag loads
#define BS_STRIDE 72    // 72  % 32 == 8
template <int MODE>
__global__ __launch_bounds__(256, 2)
void gemm_tf32_kernel(const float* __restrict__ A, const float* __restrict__ W,
                      const float* __restrict__ bias, const float* __restrict__ res,
                      float* __restrict__ C, int M, int N, int K) {
    __shared__ float As[16][AS_STRIDE];   // [k][m]
    __shared__ float Bs[16][BS_STRIDE];   // [k][n]

    int tid  = threadIdx.x;
    int lane = tid & 31;
    int wid  = tid >> 5;
    int gid  = lane >> 2;        // 0..7
    int tig  = lane & 3;         // 0..3
    int wm   = (wid & 3) * 32;   // warp m offset within block
    int wn   = (wid >> 2) * 32;  // warp n offset within block

    int m0 = blockIdx.y * 128, n0 = blockIdx.x * 64;

    float acc[2][4][4];
#pragma unroll
    for (int i = 0; i < 2; i++)
#pragma unroll
        for (int j = 0; j < 4; j++)
#pragma unroll
            for (int t = 0; t < 4; t++) acc[i][j][t] = 0.f;

    for (int k0 = 0; k0 < K; k0 += 16) {
        // load A tile 128x16 as float4 (512 float4s / 256 threads = 2 each)
#pragma unroll
        for (int j = 0; j < 2; j++) {
            int idx = j * 256 + tid;
            int r = idx >> 2, c4 = (idx & 3) * 4;
            float4 v = *reinterpret_cast<const float4*>(A + (size_t)(m0 + r) * K + k0 + c4);
            As[c4 + 0][r] = v.x; As[c4 + 1][r] = v.y;
            As[c4 + 2][r] = v.z; As[c4 + 3][r] = v.w;
        }
        // load B tile 64x16 as float4 (256 float4s / 256 threads = 1 each)
        {
            int r = tid >> 2, c4 = (tid & 3) * 4;
            float4 v = *reinterpret_cast<const float4*>(W + (size_t)(n0 + r) * K + k0 + c4);
            Bs[c4 + 0][r] = v.x; Bs[c4 + 1][r] = v.y;
            Bs[c4 + 2][r] = v.z; Bs[c4 + 3][r] = v.w;
        }
        __syncthreads();

#pragma unroll
        for (int ks = 0; ks < 16; ks += 8) {
            // A fragments (2 m-frags), split hi/lo
            unsigned ahi[2][4], alo[2][4];
#pragma unroll
            for (int mf = 0; mf < 2; mf++) {
                int mb = wm + mf * 16;
                float f0 = As[ks + tig    ][mb + gid    ];
                float f1 = As[ks + tig    ][mb + gid + 8];
                float f2 = As[ks + tig + 4][mb + gid    ];
                float f3 = As[ks + tig + 4][mb + gid + 8];
                ahi[mf][0] = tf32_of(f0); alo[mf][0] = tf32_of(f0 - __uint_as_float(ahi[mf][0]));
                ahi[mf][1] = tf32_of(f1); alo[mf][1] = tf32_of(f1 - __uint_as_float(ahi[mf][1]));
                ahi[mf][2] = tf32_of(f2); alo[mf][2] = tf32_of(f2 - __uint_as_float(ahi[mf][2]));
                ahi[mf][3] = tf32_of(f3); alo[mf][3] = tf32_of(f3 - __uint_as_float(ahi[mf][3]));
            }
            // B fragments (4 n-frags), split hi/lo
            unsigned bhi[4][2], blo[4][2];
#pragma unroll
            for (int nf = 0; nf < 4; nf++) {
                int nb = wn + nf * 8;
                float f0 = Bs[ks + tig    ][nb + gid];
                float f1 = Bs[ks + tig + 4][nb + gid];
                bhi[nf][0] = tf32_of(f0); blo[nf][0] = tf32_of(f0 - __uint_as_float(bhi[nf][0]));
                bhi[nf][1] = tf32_of(f1); blo[nf][1] = tf32_of(f1 - __uint_as_float(bhi[nf][1]));
            }
#pragma unroll
            for (int mf = 0; mf < 2; mf++)
#pragma unroll
                for (int nf = 0; nf < 4; nf++) {
                    mma_tf32(acc[mf][nf], ahi[mf][0], ahi[mf][1], ahi[mf][2], ahi[mf][3],
                             bhi[nf][0], bhi[nf][1]);
                    mma_tf32(acc[mf][nf], ahi[mf][0], ahi[mf][1], ahi[mf][2], ahi[mf][3],
                             blo[nf][0], blo[nf][1]);
                    mma_tf32(acc[mf][nf], alo[mf][0], alo[mf][1], alo[mf][2], alo[mf][3],
                             bhi[nf][0], bhi[nf][1]);
                }
        }
        __syncthreads();
    }

    // epilogue: c0 (r, c), c1 (r, c+1), c2 (r+8, c), c3 (r+8, c+1)
#pragma unroll
    for (int mf = 0; mf < 2; mf++) {
        int r = m0 + wm + mf * 16 + gid;
#pragma unroll
        for (int nf = 0; nf < 4; nf++) {
            int c = n0 + wn + nf * 8 + tig * 2;
#pragma unroll
            for (int half = 0; half < 2; half++) {
                int rr = r + half * 8;
#pragma unroll
                for (int cc = 0; cc < 2; cc++) {
                    float v = acc[mf][nf][half * 2 + cc] + bias[c + cc];
                    if (MODE == 1) v += res[(size_t)rr * N + c + cc];
                    if (MODE == 2) v = 0.5f * v * (1.0f + erff(v * 0.7071067811865476f));
                    C[(size_t)rr * N + c + cc] = v;
                }
            }
        }
    }
}

// ---------------- attention: block = (q-tile of 16, head, batch) ----------------
__global__ __launch_bounds__(256)
void attn_kernel(const float* __restrict__ qkv, const float* __restrict__ bppm,
                 const float* __restrict__ pair_w, const float* __restrict__ pair_b,
                 const float* __restrict__ relpos_w, const float* __restrict__ relpos_b,
                 float* __restrict__ o) {
    int qt = blockIdx.x;   // 0..31
    int h  = blockIdx.y;   // 0..5
    int b  = blockIdx.z;   // 0..31

    __shared__ float Qs[16][32];
    __shared__ float S[16][513];
    __shared__ float rel[BINS];
    __shared__ float red[16][16];
    __shared__ float rowmax[16], rowsum[16];
    __shared__ float msk[512];

    int tid = threadIdx.x;
    int qr = tid >> 4, kt = tid & 15;
    int q = qt * 16 + qr;

    // load Q tile (16x32)
#pragma unroll
    for (int j = 0; j < 2; j++) {
        int id = tid + j * 256;
        int r = id >> 5, d = id & 31;
        Qs[r][d] = qkv[((size_t)(b * LL + qt * 16 + r)) * QKVN + h * DHH + d];
    }
    if (tid < BINS) rel[tid] = relpos_w[h * BINS + tid];
    for (int k = tid; k < 512; k += 256) msk[k] = g_maskf[b * LL + k];
    __syncthreads();

    float pw   = pair_w[h];
    float addc = pair_b[h] + relpos_b[h];
    const float scale = 0.17677669529663687f;  // 1/sqrt(32)

    // phase 2: scores
    for (int k = kt; k < 512; k += 16) {
        const float4* K4 = reinterpret_cast<const float4*>(
            qkv + ((size_t)(b * LL + k)) * QKVN + DDIM + h * DHH);
        float dot = 0.f;
#pragma unroll
        for (int d4 = 0; d4 < 8; d4++) {
            float4 kv = K4[d4];
            dot += Qs[qr][d4*4+0]*kv.x + Qs[qr][d4*4+1]*kv.y
                 + Qs[qr][d4*4+2]*kv.z + Qs[qr][d4*4+3]*kv.w;
        }
        int diff = q - k;
        diff = max(-KCLIP, min(KCLIP, diff));
        float sv = dot * scale
                 + bppm[((size_t)b * LL + q) * LL + k] * pw
                 + addc + rel[diff + KCLIP];
        if (msk[k] == 0.f) sv = -1e9f;
        S[qr][k] = sv;
    }
    __syncthreads();

    // phase 3: softmax (two-pass over smem row)
    float lmax = -1e30f;
    for (int k = kt; k < 512; k += 16) lmax = fmaxf(lmax, S[qr][k]);
    red[qr][kt] = lmax;
    __syncthreads();
    if (tid < 16) {
        float m = red[tid][0];
#pragma unroll
        for (int j = 1; j < 16; j++) m = fmaxf(m, red[tid][j]);
        rowmax[tid] = m;
    }
    __syncthreads();
    float rm = rowmax[qr];
    float lsum = 0.f;
    for (int k = kt; k < 512; k += 16) {
        float e = __expf(S[qr][k] - rm);
        S[qr][k] = e;
        lsum += e;
    }
    red[qr][kt] = lsum;
    __syncthreads();
    if (tid < 16) {
        float s2 = 0.f;
#pragma unroll
        for (int j = 0; j < 16; j++) s2 += red[tid][j];
        rowsum[tid] = s2;
    }
    __syncthreads();

    // phase 4: O = attn @ V ; thread handles (qr, d=2*kt, d=2*kt+1) via float2
    float inv = 1.0f / rowsum[qr];
    float acc0 = 0.f, acc1 = 0.f;
    const float* Vbase = qkv + (size_t)(b * LL) * QKVN + 2 * DDIM + h * DHH;
#pragma unroll 8
    for (int k = 0; k < 512; k++) {
        float s = S[qr][k];
        float2 v2 = reinterpret_cast<const float2*>(Vbase + (size_t)k * QKVN)[kt];
        acc0 += s * v2.x;
        acc1 += s * v2.y;
    }
    size_t orow = ((size_t)(b * LL + q)) * DDIM + h * DHH;
    o[orow + 2*kt]     = acc0 * inv;
    o[orow + 2*kt + 1] = acc1 * inv;
}

// ---------------- final projection: warp per row, 2 outputs ----------------
__global__ void proj_kernel(const float* __restrict__ x,
                            const float* __restrict__ pw,
                            const float* __restrict__ pb,
                            float* __restrict__ out) {
    int row  = blockIdx.x * 8 + (threadIdx.x >> 5);
    int lane = threadIdx.x & 31;
    const float* xr = x + (size_t)row * DDIM;
    float d0 = 0.f, d1 = 0.f;
#pragma unroll
    for (int j = 0; j < 6; j++) {
        int c = lane + 32*j;
        float v = xr[c];
        d0 += v * pw[c];
        d1 += v * pw[DDIM + c];
    }
#pragma unroll
    for (int o = 16; o; o >>= 1) {
        d0 += __shfl_xor_sync(0xffffffffu, d0, o);
        d1 += __shfl_xor_sync(0xffffffffu, d1, o);
    }
    if (lane == 0) {
        out[row*2 + 0] = d0 + pb[0];
        out[row*2 + 1] = d1 + pb[1];
    }
}

// ---------------- launch ----------------
extern "C" void kernel_launch(void* const* d_in, const int* in_sizes, int n_in,
                              void* d_out, int out_size) {
    const int*   seq      = (const int*)  d_in[0];
    const void*  mask     =               d_in[1];
    const float* bppm     = (const float*)d_in[2];
    const float* emb      = (const float*)d_in[3];
    const float* pair_w   = (const float*)d_in[4];
    const float* pair_b   = (const float*)d_in[5];
    const float* relpos_w = (const float*)d_in[6];
    const float* relpos_b = (const float*)d_in[7];
    const float* ln1_s    = (const float*)d_in[8];
    const float* ln1_b    = (const float*)d_in[9];
    const float* qkv_w    = (const float*)d_in[10];
    const float* qkv_b    = (const float*)d_in[11];
    const float* out_w    = (const float*)d_in[12];
    const float* out_b    = (const float*)d_in[13];
    const float* ln2_s    = (const float*)d_in[14];
    const float* ln2_b    = (const float*)d_in[15];
    const float* ff1_w    = (const float*)d_in[16];
    const float* ff1_b    = (const float*)d_in[17];
    const float* ff2_w    = (const float*)d_in[18];
    const float* ff2_b    = (const float*)d_in[19];
    const float* proj_w   = (const float*)d_in[20];
    const float* proj_b   = (const float*)d_in[21];
    float* out = (float*)d_out;

    float *x, *h, *qkvB, *o, *ff;
    cudaGetSymbolAddress((void**)&x,    g_x);
    cudaGetSymbolAddress((void**)&h,    g_h);
    cudaGetSymbolAddress((void**)&qkvB, g_qkv);
    cudaGetSymbolAddress((void**)&o,    g_o);
    cudaGetSymbolAddress((void**)&ff,   g_ff);

    // mask dtype detection + expansion (deterministic)
    mask_reset_kernel<<<1, 1>>>();
    mask_detect_kernel<<<(NROW + 255) / 256, 256>>>((const unsigned char*)mask);
    mask_expand_kernel<<<(NROW + 255) / 256, 256>>>(mask);

    // embedding
    embed_kernel<<<(NROW * DDIM) / 256, 256>>>(seq, emb, x);

    dim3 gQKV(QKVN / 64, NROW / 128);   // 9 x 128
    dim3 gOUT(DDIM / 64, NROW / 128);   // 3 x 128
    dim3 gFF1(FFN  / 64, NROW / 128);   // 12 x 128
    dim3 gATT(LL / 16, HH, BB);         // 32 x 6 x 32

    for (int i = 0; i < DEPTH; i++) {
        // h = LN1(x)
        ln_kernel<<<NROW / 8, 256>>>(x, ln1_s + i*DDIM, ln1_b + i*DDIM, h);
        // qkv = h @ qkv_w^T + qkv_b
        gemm_tf32_kernel<0><<<gQKV, 256>>>(h, qkv_w + (size_t)i*QKVN*DDIM,
                                           qkv_b + i*QKVN, nullptr, qkvB,
                                           NROW, QKVN, DDIM);
        // attention -> o
        attn_kernel<<<gATT, 256>>>(qkvB, bppm, pair_w, pair_b,
                                   relpos_w, relpos_b, o);
        // x = x + o @ out_w^T + out_b
        gemm_tf32_kernel<1><<<gOUT, 256>>>(o, out_w + (size_t)i*DDIM*DDIM,
                                           out_b + i*DDIM, x, x,
                                           NROW, DDIM, DDIM);
        // h = LN2(x)
        ln_kernel<<<NROW / 8, 256>>>(x, ln2_s + i*DDIM, ln2_b + i*DDIM, h);
        // ff = gelu(h @ ff1_w^T + ff1_b)
        gemm_tf32_kernel<2><<<gFF1, 256>>>(h, ff1_w + (size_t)i*FFN*DDIM,
                                           ff1_b + i*FFN, nullptr, ff,
                                           NROW, FFN, DDIM);
        // x = x + ff @ ff2_w^T + ff2_b
        gemm_tf32_kernel<1><<<gOUT, 256>>>(ff, ff2_w + (size_t)i*DDIM*FFN,
                                           ff2_b + i*DDIM, x, x,
                                           NROW, DDIM, FFN);
    }

    // out = x @ proj_w^T + proj_b
    proj_kernel<<<NROW / 8, 256>>>(x, proj_w, proj_b, out);
}

// round 3
// speedup vs baseline: 4.2430x; 3.8146x over previous
#include <cuda_runtime.h>
#include <cuda_bf16.h>
#include <math.h>

// ---------------- problem constants ----------------
#define BB   32
#define LL   512
#define DDIM 192
#define DEPTH 12
#define HH   6
#define DHH  32
#define KCLIP 32
#define BINS 65
#define NROW (BB*LL)          // 16384
#define QKVN (3*DDIM)         // 576
#define FFN  (4*DDIM)         // 768

// ---------------- scratch (static device arrays; no allocation) ----------------
__device__ float g_x  [NROW*DDIM];
__device__ float g_h  [NROW*DDIM];
__device__ float g_qkv[NROW*QKVN];
__device__ float g_o  [NROW*DDIM];
__device__ float g_ff [NROW*FFN];
__device__ float g_maskf[NROW];
__device__ int   g_mask_is_u8;

// ---------------- mask dtype detection ----------------
__global__ void mask_reset_kernel() { g_mask_is_u8 = 0; }

__global__ void mask_detect_kernel(const unsigned char* __restrict__ m) {
    int i = blockIdx.x * 256 + threadIdx.x;
    if (i < NROW && (i & 3) != 0 && m[i] != 0) atomicOr(&g_mask_is_u8, 1);
}

__global__ void mask_expand_kernel(const void* __restrict__ m) {
    int i = blockIdx.x * 256 + threadIdx.x;
    if (i >= NROW) return;
    int v;
    if (g_mask_is_u8) v = ((const unsigned char*)m)[i];
    else              v = ((const int*)m)[i];
    g_maskf[i] = v ? 1.0f : 0.0f;
}

// ---------------- embedding ----------------
__global__ void embed_kernel(const int* __restrict__ seq,
                             const float* __restrict__ emb,
                             float* __restrict__ x) {
    int i = blockIdx.x * 256 + threadIdx.x;
    if (i >= NROW * DDIM) return;
    int row = i / DDIM, c = i - row * DDIM;
    x[i] = emb[seq[row] * DDIM + c];
}

// ---------------- layernorm (warp per row) ----------------
__global__ void ln_kernel(const float* __restrict__ x,
                          const float* __restrict__ s,
                          const float* __restrict__ b,
                          float* __restrict__ out) {
    int row  = blockIdx.x * 8 + (threadIdx.x >> 5);
    int lane = threadIdx.x & 31;
    const float* xr = x + (size_t)row * DDIM;
    float v[6], sum = 0.f;
#pragma unroll
    for (int j = 0; j < 6; j++) { v[j] = xr[lane + 32*j]; sum += v[j]; }
#pragma unroll
    for (int o = 16; o; o >>= 1) sum += __shfl_xor_sync(0xffffffffu, sum, o);
    float mu = sum * (1.0f / DDIM);
    float vs = 0.f;
#pragma unroll
    for (int j = 0; j < 6; j++) { float d = v[j] - mu; vs += d * d; }
#pragma unroll
    for (int o = 16; o; o >>= 1) vs += __shfl_xor_sync(0xffffffffu, vs, o);
    float inv = rsqrtf(vs * (1.0f / DDIM) + 1e-5f);
    float* orow = out + (size_t)row * DDIM;
#pragma unroll
    for (int j = 0; j < 6; j++) {
        int c = lane + 32*j;
        orow[c] = (v[j] - mu) * inv * s[c] + b[c];
    }
}

// ---------------- tf32 helpers ----------------
__device__ __forceinline__ unsigned tf32_of(float x) {
    unsigned u;
    asm("cvt.rna.tf32.f32 %0, %1;" : "=r"(u) : "f"(x));
    return u;
}

__device__ __forceinline__ void mma_tf32(float* c,
                                         unsigned a0, unsigned a1, unsigned a2, unsigned a3,
                                         unsigned b0, unsigned b1) {
    asm("mma.sync.aligned.m16n8k8.row.col.f32.tf32.tf32.f32 "
        "{%0,%1,%2,%3},{%4,%5,%6,%7},{%8,%9},{%0,%1,%2,%3};"
        : "+f"(c[0]), "+f"(c[1]), "+f"(c[2]), "+f"(c[3])
        : "r"(a0), "r"(a1), "r"(a2), "r"(a3), "r"(b0), "r"(b1));
}

// ---------------- bf16 helpers ----------------
__device__ __forceinline__ unsigned pack_bf16(float lo, float hi) {
    // word low16 = bf16(lo), high16 = bf16(hi)
    unsigned r;
    asm("cvt.rn.bf16x2.f32 %0, %1, %2;" : "=r"(r) : "f"(hi), "f"(lo));
    return r;
}
__device__ __forceinline__ unsigned lo_residual(unsigned hiw, float lo, float hi) {
    float h0 = __uint_as_float(hiw << 16);
    float h1 = __uint_as_float(hiw & 0xffff0000u);
    return pack_bf16(lo - h0, hi - h1);
}
__device__ __forceinline__ void mma_bf16(float* c,
                                         unsigned a0, unsigned a1, unsigned a2, unsigned a3,
                                         unsigned b0, unsigned b1) {
    asm("mma.sync.aligned.m16n8k16.row.col.f32.bf16.bf16.f32 "
        "{%0,%1,%2,%3},{%4,%5,%6,%7},{%8,%9},{%0,%1,%2,%3};"
        : "+f"(c[0]), "+f"(c[1]), "+f"(c[2]), "+f"(c[3])
        : "r"(a0), "r"(a1), "r"(a2), "r"(a3), "r"(b0), "r"(b1));
}

// ---------------- TF32 tensor-core GEMM (unchanged from R2) --------------
#define AS_STRIDE 136
#define BS_STRIDE 72
template <int MODE>
__global__ __launch_bounds__(256, 2)
void gemm_tf32_kernel(const float* __restrict__ A, const float* __restrict__ W,
                      const float* __restrict__ bias, const float* __restrict__ res,
                      float* __restrict__ C, int M, int N, int K) {
    __shared__ float As[16][AS_STRIDE];
    __shared__ float Bs[16][BS_STRIDE];

    int tid  = threadIdx.x;
    int lane = tid & 31;
    int wid  = tid >> 5;
    int gid  = lane >> 2;
    int tig  = lane & 3;
    int wm   = (wid & 3) * 32;
    int wn   = (wid >> 2) * 32;

    int m0 = blockIdx.y * 128, n0 = blockIdx.x * 64;

    float acc[2][4][4];
#pragma unroll
    for (int i = 0; i < 2; i++)
#pragma unroll
        for (int j = 0; j < 4; j++)
#pragma unroll
            for (int t = 0; t < 4; t++) acc[i][j][t] = 0.f;

    for (int k0 = 0; k0 < K; k0 += 16) {
#pragma unroll
        for (int j = 0; j < 2; j++) {
            int idx = j * 256 + tid;
            int r = idx >> 2, c4 = (idx & 3) * 4;
            float4 v = *reinterpret_cast<const float4*>(A + (size_t)(m0 + r) * K + k0 + c4);
            As[c4 + 0][r] = v.x; As[c4 + 1][r] = v.y;
            As[c4 + 2][r] = v.z; As[c4 + 3][r] = v.w;
        }
        {
            int r = tid >> 2, c4 = (tid & 3) * 4;
            float4 v = *reinterpret_cast<const float4*>(W + (size_t)(n0 + r) * K + k0 + c4);
            Bs[c4 + 0][r] = v.x; Bs[c4 + 1][r] = v.y;
            Bs[c4 + 2][r] = v.z; Bs[c4 + 3][r] = v.w;
        }
        __syncthreads();

#pragma unroll
        for (int ks = 0; ks < 16; ks += 8) {
            unsigned ahi[2][4], alo[2][4];
#pragma unroll
            for (int mf = 0; mf < 2; mf++) {
                int mb = wm + mf * 16;
                float f0 = As[ks + tig    ][mb + gid    ];
                float f1 = As[ks + tig    ][mb + gid + 8];
                float f2 = As[ks + tig + 4][mb + gid    ];
                float f3 = As[ks + tig + 4][mb + gid + 8];
                ahi[mf][0] = tf32_of(f0); alo[mf][0] = tf32_of(f0 - __uint_as_float(ahi[mf][0]));
                ahi[mf][1] = tf32_of(f1); alo[mf][1] = tf32_of(f1 - __uint_as_float(ahi[mf][1]));
                ahi[mf][2] = tf32_of(f2); alo[mf][2] = tf32_of(f2 - __uint_as_float(ahi[mf][2]));
                ahi[mf][3] = tf32_of(f3); alo[mf][3] = tf32_of(f3 - __uint_as_float(ahi[mf][3]));
            }
            unsigned bhi[4][2], blo[4][2];
#pragma unroll
            for (int nf = 0; nf < 4; nf++) {
                int nb = wn + nf * 8;
                float f0 = Bs[ks + tig    ][nb + gid];
                float f1 = Bs[ks + tig + 4][nb + gid];
                bhi[nf][0] = tf32_of(f0); blo[nf][0] = tf32_of(f0 - __uint_as_float(bhi[nf][0]));
                bhi[nf][1] = tf32_of(f1); blo[nf][1] = tf32_of(f1 - __uint_as_float(bhi[nf][1]));
            }
#pragma unroll
            for (int mf = 0; mf < 2; mf++)
#pragma unroll
                for (int nf = 0; nf < 4; nf++) {
                    mma_tf32(acc[mf][nf], ahi[mf][0], ahi[mf][1], ahi[mf][2], ahi[mf][3],
                             bhi[nf][0], bhi[nf][1]);
                    mma_tf32(acc[mf][nf], ahi[mf][0], ahi[mf][1], ahi[mf][2], ahi[mf][3],
                             blo[nf][0], blo[nf][1]);
                    mma_tf32(acc[mf][nf], alo[mf][0], alo[mf][1], alo[mf][2], alo[mf][3],
                             bhi[nf][0], bhi[nf][1]);
                }
        }
        __syncthreads();
    }

#pragma unroll
    for (int mf = 0; mf < 2; mf++) {
        int r = m0 + wm + mf * 16 + gid;
#pragma unroll
        for (int nf = 0; nf < 4; nf++) {
            int c = n0 + wn + nf * 8 + tig * 2;
#pragma unroll
            for (int half = 0; half < 2; half++) {
                int rr = r + half * 8;
#pragma unroll
                for (int cc = 0; cc < 2; cc++) {
                    float v = acc[mf][nf][half * 2 + cc] + bias[c + cc];
                    if (MODE == 1) v += res[(size_t)rr * N + c + cc];
                    if (MODE == 2) v = 0.5f * v * (1.0f + erff(v * 0.7071067811865476f));
                    C[(size_t)rr * N + c + cc] = v;
                }
            }
        }
    }
}

// ================= flash attention with bf16-split mma =================
// block = (qtile of 128, head, batch); 256 threads = 8 warps; warp = 16 q rows.
// K/V streamed in tiles of 128 kpos; online softmax in fp32.
// smem word offsets:
#define KQ_STRIDE 20            // words per row (16 used + 4 pad)
#define V_STRIDE  69            // words per row (64 used + 5 pad)
#define OFF_KH 0
#define OFF_KL 2560
#define OFF_QH 5120
#define OFF_QL 7680
#define OFF_VH 10240
#define OFF_VL 12448
#define OFF_REL 14656
#define OFF_MSK 14721
#define SMEM_ATT_WORDS 15240
#define SMEM_ATT_BYTES (SMEM_ATT_WORDS*4)

__global__ __launch_bounds__(256, 1)
void attn_mma_kernel(const float* __restrict__ qkv, const float* __restrict__ bppm,
                     const float* __restrict__ pair_w, const float* __restrict__ pair_b,
                     const float* __restrict__ relpos_w, const float* __restrict__ relpos_b,
                     float* __restrict__ o) {
    extern __shared__ unsigned sm[];
    unsigned* KsHi = sm + OFF_KH;
    unsigned* KsLo = sm + OFF_KL;
    unsigned* QsHi = sm + OFF_QH;
    unsigned* QsLo = sm + OFF_QL;
    unsigned* VsHi = sm + OFF_VH;
    unsigned* VsLo = sm + OFF_VL;
    float*    rel  = (float*)(sm + OFF_REL);
    float*    msk  = (float*)(sm + OFF_MSK);

    const int tid  = threadIdx.x;
    const int lane = tid & 31;
    const int w    = tid >> 5;
    const int qt   = blockIdx.x;      // 0..3
    const int h    = blockIdx.y;      // 0..5
    const int b    = blockIdx.z;      // 0..31
    const int q0   = qt * 128;
    const int wq   = w * 16;          // warp's q-row offset in tile

    const int g    = lane >> 2;       // 0..7 (row in frag)
    const int tg   = lane & 3;        // 0..3

    // ---- stage Q (128x32) as bf16 hi/lo ----
#pragma unroll
    for (int j = 0; j < 4; j++) {
        int r  = w * 16 + j * 4 + (lane >> 3);
        int c4 = (lane & 7) * 4;
        float4 v = *reinterpret_cast<const float4*>(
            qkv + (size_t)(b * LL + q0 + r) * QKVN + h * DHH + c4);
        unsigned h0 = pack_bf16(v.x, v.y);
        unsigned h1 = pack_bf16(v.z, v.w);
        int base = r * KQ_STRIDE + (c4 >> 1);
        QsHi[base]     = h0;
        QsHi[base + 1] = h1;
        QsLo[base]     = lo_residual(h0, v.x, v.y);
        QsLo[base + 1] = lo_residual(h1, v.z, v.w);
    }
    if (tid < BINS) rel[tid] = relpos_w[h * BINS + tid];
    for (int k = tid; k < LL; k += 256) msk[k] = g_maskf[b * LL + k];
    __syncthreads();

    const float pw    = pair_w[h];
    const float addc  = pair_b[h] + relpos_b[h];
    const float scale = 0.17677669529663687f;

    // softmax / output state
    float m0v = -1e30f, m1v = -1e30f;
    float lp0 = 0.f,   lp1 = 0.f;
    float Oacc[4][4];
#pragma unroll
    for (int i = 0; i < 4; i++)
#pragma unroll
        for (int j = 0; j < 4; j++) Oacc[i][j] = 0.f;

    const int row0 = q0 + wq + g;     // global q row (frag rows row0, row0+8)

    for (int kt = 0; kt < 4; kt++) {
        const int k0 = kt * 128;

        // ---- stage K tile (128x32) ----
#pragma unroll
        for (int j = 0; j < 4; j++) {
            int r  = w * 16 + j * 4 + (lane >> 3);
            int c4 = (lane & 7) * 4;
            float4 v = *reinterpret_cast<const float4*>(
                qkv + (size_t)(b * LL + k0 + r) * QKVN + DDIM + h * DHH + c4);
            unsigned h0 = pack_bf16(v.x, v.y);
            unsigned h1 = pack_bf16(v.z, v.w);
            int base = r * KQ_STRIDE + (c4 >> 1);
            KsHi[base]     = h0;
            KsHi[base + 1] = h1;
            KsLo[base]     = lo_residual(h0, v.x, v.y);
            KsLo[base + 1] = lo_residual(h1, v.z, v.w);
        }
        // ---- stage V tile transposed: Vs[d][kpos-pair] ----
#pragma unroll
        for (int j = 0; j < 2; j++) {
            int p  = w * 8 + j * 4 + (lane >> 3);   // kpos pair index 0..63
            int d4 = (lane & 7) * 4;
            const float* base = qkv + (size_t)(b * LL + k0 + 2 * p) * QKVN + 2 * DDIM + h * DHH + d4;
            float4 v0 = *reinterpret_cast<const float4*>(base);
            float4 v1 = *reinterpret_cast<const float4*>(base + QKVN);
            float a0[4] = {v0.x, v0.y, v0.z, v0.w};
            float a1[4] = {v1.x, v1.y, v1.z, v1.w};
#pragma unroll
            for (int i = 0; i < 4; i++) {
                unsigned hw = pack_bf16(a0[i], a1[i]);   // low = kpos 2p, high = 2p+1
                VsHi[(d4 + i) * V_STRIDE + p] = hw;
                VsLo[(d4 + i) * V_STRIDE + p] = lo_residual(hw, a0[i], a1[i]);
            }
        }
        __syncthreads();

        // ---- S = Q K^T (bf16 split, 3 passes) ----
        float S[16][4];
#pragma unroll
        for (int nt = 0; nt < 16; nt++)
#pragma unroll
            for (int c = 0; c < 4; c++) S[nt][c] = 0.f;

#pragma unroll
        for (int ks = 0; ks < 2; ks++) {
            int ab = (wq + g) * KQ_STRIDE + ks * 8 + tg;
            unsigned aH0 = QsHi[ab],              aH1 = QsHi[ab + 8 * KQ_STRIDE];
            unsigned aH2 = QsHi[ab + 4],          aH3 = QsHi[ab + 8 * KQ_STRIDE + 4];
            unsigned aL0 = QsLo[ab],              aL1 = QsLo[ab + 8 * KQ_STRIDE];
            unsigned aL2 = QsLo[ab + 4],          aL3 = QsLo[ab + 8 * KQ_STRIDE + 4];
#pragma unroll
            for (int nt = 0; nt < 16; nt++) {
                int bb = (nt * 8 + g) * KQ_STRIDE + ks * 8 + tg;
                unsigned bH0 = KsHi[bb], bH1 = KsHi[bb + 4];
                unsigned bL0 = KsLo[bb], bL1 = KsLo[bb + 4];
                mma_bf16(S[nt], aH0, aH1, aH2, aH3, bH0, bH1);
                mma_bf16(S[nt], aH0, aH1, aH2, aH3, bL0, bL1);
                mma_bf16(S[nt], aL0, aL1, aL2, aL3, bH0, bH1);
            }
        }

        // ---- scale + bias + mask ----
#pragma unroll
        for (int nt = 0; nt < 16; nt++) {
            int col = k0 + nt * 8 + tg * 2;
            float2 bp0 = *reinterpret_cast<const float2*>(
                bppm + ((size_t)(b * LL + row0)) * LL + col);
            float2 bp1 = *reinterpret_cast<const float2*>(
                bppm + ((size_t)(b * LL + row0 + 8)) * LL + col);
            int d00 = min(KCLIP, max(-KCLIP, row0 - col))     + KCLIP;
            int d01 = min(KCLIP, max(-KCLIP, row0 - col - 1)) + KCLIP;
            int d10 = min(KCLIP, max(-KCLIP, row0 + 8 - col))     + KCLIP;
            int d11 = min(KCLIP, max(-KCLIP, row0 + 8 - col - 1)) + KCLIP;
            float mk0 = msk[col], mk1 = msk[col + 1];
            float s0 = S[nt][0] * scale + bp0.x * pw + rel[d00] + addc;
            float s1 = S[nt][1] * scale + bp0.y * pw + rel[d01] + addc;
            float s2 = S[nt][2] * scale + bp1.x * pw + rel[d10] + addc;
            float s3 = S[nt][3] * scale + bp1.y * pw + rel[d11] + addc;
            S[nt][0] = (mk0 != 0.f) ? s0 : -1e9f;
            S[nt][1] = (mk1 != 0.f) ? s1 : -1e9f;
            S[nt][2] = (mk0 != 0.f) ? s2 : -1e9f;
            S[nt][3] = (mk1 != 0.f) ? s3 : -1e9f;
        }

        // ---- online softmax update ----
        float t0 = -1e30f, t1 = -1e30f;
#pragma unroll
        for (int nt = 0; nt < 16; nt++) {
            t0 = fmaxf(t0, fmaxf(S[nt][0], S[nt][1]));
            t1 = fmaxf(t1, fmaxf(S[nt][2], S[nt][3]));
        }
        t0 = fmaxf(t0, __shfl_xor_sync(0xffffffffu, t0, 1));
        t0 = fmaxf(t0, __shfl_xor_sync(0xffffffffu, t0, 2));
        t1 = fmaxf(t1, __shfl_xor_sync(0xffffffffu, t1, 1));
        t1 = fmaxf(t1, __shfl_xor_sync(0xffffffffu, t1, 2));

        float mn0 = fmaxf(m0v, t0), mn1 = fmaxf(m1v, t1);
        float al0 = __expf(m0v - mn0), al1 = __expf(m1v - mn1);
        m0v = mn0; m1v = mn1;

        float sum0 = 0.f, sum1 = 0.f;
#pragma unroll
        for (int nt = 0; nt < 16; nt++) {
            S[nt][0] = __expf(S[nt][0] - m0v);
            S[nt][1] = __expf(S[nt][1] - m0v);
            S[nt][2] = __expf(S[nt][2] - m1v);
            S[nt][3] = __expf(S[nt][3] - m1v);
            sum0 += S[nt][0] + S[nt][1];
            sum1 += S[nt][2] + S[nt][3];
        }
        lp0 = lp0 * al0 + sum0;
        lp1 = lp1 * al1 + sum1;
#pragma unroll
        for (int nt = 0; nt < 4; nt++) {
            Oacc[nt][0] *= al0; Oacc[nt][1] *= al0;
            Oacc[nt][2] *= al1; Oacc[nt][3] *= al1;
        }

        // ---- O += P V (bf16 split, 3 passes) ----
#pragma unroll
        for (int j = 0; j < 8; j++) {
            unsigned pH0 = pack_bf16(S[2*j][0],   S[2*j][1]);
            unsigned pH1 = pack_bf16(S[2*j][2],   S[2*j][3]);
            unsigned pH2 = pack_bf16(S[2*j+1][0], S[2*j+1][1]);
            unsigned pH3 = pack_bf16(S[2*j+1][2], S[2*j+1][3]);
            unsigned pL0 = lo_residual(pH0, S[2*j][0],   S[2*j][1]);
            unsigned pL1 = lo_residual(pH1, S[2*j][2],   S[2*j][3]);
            unsigned pL2 = lo_residual(pH2, S[2*j+1][0], S[2*j+1][1]);
            unsigned pL3 = lo_residual(pH3, S[2*j+1][2], S[2*j+1][3]);
#pragma unroll
            for (int nt = 0; nt < 4; nt++) {
                int bb = (nt * 8 + g) * V_STRIDE + j * 8 + tg;
                unsigned bH0 = VsHi[bb], bH1 = VsHi[bb + 4];
                unsigned bL0 = VsLo[bb], bL1 = VsLo[bb + 4];
                mma_bf16(Oacc[nt], pH0, pH1, pH2, pH3, bH0, bH1);
                mma_bf16(Oacc[nt], pH0, pH1, pH2, pH3, bL0, bL1);
                mma_bf16(Oacc[nt], pL0, pL1, pL2, pL3, bH0, bH1);
            }
        }
        __syncthreads();
    }

    // ---- epilogue: normalize and write ----
    float l0 = lp0 + __shfl_xor_sync(0xffffffffu, lp0, 1);
    l0 += __shfl_xor_sync(0xffffffffu, l0, 2);
    float l1 = lp1 + __shfl_xor_sync(0xffffffffu, lp1, 1);
    l1 += __shfl_xor_sync(0xffffffffu, l1, 2);
    float inv0 = 1.0f / l0, inv1 = 1.0f / l1;

#pragma unroll
    for (int nt = 0; nt < 4; nt++) {
        int d = h * DHH + nt * 8 + tg * 2;
        float2 o0 = make_float2(Oacc[nt][0] * inv0, Oacc[nt][1] * inv0);
        float2 o1 = make_float2(Oacc[nt][2] * inv1, Oacc[nt][3] * inv1);
        *reinterpret_cast<float2*>(o + ((size_t)(b * LL + row0))     * DDIM + d) = o0;
        *reinterpret_cast<float2*>(o + ((size_t)(b * LL + row0 + 8)) * DDIM + d) = o1;
    }
}

// ---------------- final projection ----------------
__global__ void proj_kernel(const float* __restrict__ x,
                            const float* __restrict__ pw,
                            const float* __restrict__ pb,
                            float* __restrict__ out) {
    int row  = blockIdx.x * 8 + (threadIdx.x >> 5);
    int lane = threadIdx.x & 31;
    const float* xr = x + (size_t)row * DDIM;
    float d0 = 0.f, d1 = 0.f;
#pragma unroll
    for (int j = 0; j < 6; j++) {
        int c = lane + 32*j;
        float v = xr[c];
        d0 += v * pw[c];
        d1 += v * pw[DDIM + c];
    }
#pragma unroll
    for (int o = 16; o; o >>= 1) {
        d0 += __shfl_xor_sync(0xffffffffu, d0, o);
        d1 += __shfl_xor_sync(0xffffffffu, d1, o);
    }
    if (lane == 0) {
        out[row*2 + 0] = d0 + pb[0];
        out[row*2 + 1] = d1 + pb[1];
    }
}

// ---------------- launch ----------------
extern "C" void kernel_launch(void* const* d_in, const int* in_sizes, int n_in,
                              void* d_out, int out_size) {
    const int*   seq      = (const int*)  d_in[0];
    const void*  mask     =               d_in[1];
    const float* bppm     = (const float*)d_in[2];
    const float* emb      = (const float*)d_in[3];
    const float* pair_w   = (const float*)d_in[4];
    const float* pair_b   = (const float*)d_in[5];
    const float* relpos_w = (const float*)d_in[6];
    const float* relpos_b = (const float*)d_in[7];
    const float* ln1_s    = (const float*)d_in[8];
    const float* ln1_b    = (const float*)d_in[9];
    const float* qkv_w    = (const float*)d_in[10];
    const float* qkv_b    = (const float*)d_in[11];
    const float* out_w    = (const float*)d_in[12];
    const float* out_b    = (const float*)d_in[13];
    const float* ln2_s    = (const float*)d_in[14];
    const float* ln2_b    = (const float*)d_in[15];
    const float* ff1_w    = (const float*)d_in[16];
    const float* ff1_b    = (const float*)d_in[17];
    const float* ff2_w    = (const float*)d_in[18];
    const float* ff2_b    = (const float*)d_in[19];
    const float* proj_w   = (const float*)d_in[20];
    const float* proj_b   = (const float*)d_in[21];
    float* out = (float*)d_out;

    float *x, *h, *qkvB, *o, *ff;
    cudaGetSymbolAddress((void**)&x,    g_x);
    cudaGetSymbolAddress((void**)&h,    g_h);
    cudaGetSymbolAddress((void**)&qkvB, g_qkv);
    cudaGetSymbolAddress((void**)&o,    g_o);
    cudaGetSymbolAddress((void**)&ff,   g_ff);

    static int attr_set = 0;
    if (!attr_set) {
        cudaFuncSetAttribute(attn_mma_kernel,
                             cudaFuncAttributeMaxDynamicSharedMemorySize, SMEM_ATT_BYTES);
        attr_set = 1;
    }

    mask_reset_kernel<<<1, 1>>>();
    mask_detect_kernel<<<(NROW + 255) / 256, 256>>>((const unsigned char*)mask);
    mask_expand_kernel<<<(NROW + 255) / 256, 256>>>(mask);

    embed_kernel<<<(NROW * DDIM) / 256, 256>>>(seq, emb, x);

    dim3 gQKV(QKVN / 64, NROW / 128);
    dim3 gOUT(DDIM / 64, NROW / 128);
    dim3 gFF1(FFN  / 64, NROW / 128);
    dim3 gATT(LL / 128, HH, BB);        // 4 x 6 x 32

    for (int i = 0; i < DEPTH; i++) {
        ln_kernel<<<NROW / 8, 256>>>(x, ln1_s + i*DDIM, ln1_b + i*DDIM, h);
        gemm_tf32_kernel<0><<<gQKV, 256>>>(h, qkv_w + (size_t)i*QKVN*DDIM,
                                           qkv_b + i*QKVN, nullptr, qkvB,
                                           NROW, QKVN, DDIM);
        attn_mma_kernel<<<gATT, 256, SMEM_ATT_BYTES>>>(qkvB, bppm, pair_w, pair_b,
                                                       relpos_w, relpos_b, o);
        gemm_tf32_kernel<1><<<gOUT, 256>>>(o, out_w + (size_t)i*DDIM*DDIM,
                                           out_b + i*DDIM, x, x,
                                           NROW, DDIM, DDIM);
        ln_kernel<<<NROW / 8, 256>>>(x, ln2_s + i*DDIM, ln2_b + i*DDIM, h);
        gemm_tf32_kernel<2><<<gFF1, 256>>>(h, ff1_w + (size_t)i*FFN*DDIM,
                                           ff1_b + i*FFN, nullptr, ff,
                                           NROW, FFN, DDIM);
        gemm_tf32_kernel<1><<<gOUT, 256>>>(ff, ff2_w + (size_t)i*DDIM*FFN,
                                           ff2_b + i*DDIM, x, x,
                                           NROW, DDIM, FFN);
    }

    proj_kernel<<<NROW / 8, 256>>>(x, proj_w, proj_b, out);
}

// round 4
// speedup vs baseline: 5.9979x; 1.4136x over previous
#include <cuda_runtime.h>
#include <cuda_bf16.h>
#include <math.h>

// ---------------- problem constants ----------------
#define BB   32
#define LL   512
#define DDIM 192
#define DEPTH 12
#define HH   6
#define DHH  32
#define KCLIP 32
#define BINS 65
#define NROW (BB*LL)          // 16384
#define QKVN (3*DDIM)         // 576
#define FFN  (4*DDIM)         // 768

// ---------------- scratch (static device arrays; no allocation) ----------------
__device__ float g_x  [NROW*DDIM];
__device__ float g_h  [NROW*DDIM];
__device__ float g_qkv[NROW*QKVN];
__device__ float g_o  [NROW*DDIM];
__device__ float g_ff [NROW*FFN];
__device__ float g_maskf[NROW];
__device__ int   g_mask_is_u8;

// ---------------- mask dtype detection ----------------
__global__ void mask_reset_kernel() { g_mask_is_u8 = 0; }

__global__ void mask_detect_kernel(const unsigned char* __restrict__ m) {
    int i = blockIdx.x * 256 + threadIdx.x;
    if (i < NROW && (i & 3) != 0 && m[i] != 0) atomicOr(&g_mask_is_u8, 1);
}

__global__ void mask_expand_kernel(const void* __restrict__ m) {
    int i = blockIdx.x * 256 + threadIdx.x;
    if (i >= NROW) return;
    int v;
    if (g_mask_is_u8) v = ((const unsigned char*)m)[i];
    else              v = ((const int*)m)[i];
    g_maskf[i] = v ? 1.0f : 0.0f;
}

// ---------------- embedding ----------------
__global__ void embed_kernel(const int* __restrict__ seq,
                             const float* __restrict__ emb,
                             float* __restrict__ x) {
    int i = blockIdx.x * 256 + threadIdx.x;
    if (i >= NROW * DDIM) return;
    int row = i / DDIM, c = i - row * DDIM;
    x[i] = emb[seq[row] * DDIM + c];
}

// ---------------- layernorm (warp per row) ----------------
__global__ void ln_kernel(const float* __restrict__ x,
                          const float* __restrict__ s,
                          const float* __restrict__ b,
                          float* __restrict__ out) {
    int row  = blockIdx.x * 8 + (threadIdx.x >> 5);
    int lane = threadIdx.x & 31;
    const float* xr = x + (size_t)row * DDIM;
    float v[6], sum = 0.f;
#pragma unroll
    for (int j = 0; j < 6; j++) { v[j] = xr[lane + 32*j]; sum += v[j]; }
#pragma unroll
    for (int o = 16; o; o >>= 1) sum += __shfl_xor_sync(0xffffffffu, sum, o);
    float mu = sum * (1.0f / DDIM);
    float vs = 0.f;
#pragma unroll
    for (int j = 0; j < 6; j++) { float d = v[j] - mu; vs += d * d; }
#pragma unroll
    for (int o = 16; o; o >>= 1) vs += __shfl_xor_sync(0xffffffffu, vs, o);
    float inv = rsqrtf(vs * (1.0f / DDIM) + 1e-5f);
    float* orow = out + (size_t)row * DDIM;
#pragma unroll
    for (int j = 0; j < 6; j++) {
        int c = lane + 32*j;
        orow[c] = (v[j] - mu) * inv * s[c] + b[c];
    }
}

// ---------------- bf16 helpers ----------------
__device__ __forceinline__ unsigned pack_bf16(float lo, float hi) {
    // word low16 = bf16(lo), high16 = bf16(hi)
    unsigned r;
    asm("cvt.rn.bf16x2.f32 %0, %1, %2;" : "=r"(r) : "f"(hi), "f"(lo));
    return r;
}
__device__ __forceinline__ unsigned lo_residual(unsigned hiw, float lo, float hi) {
    float h0 = __uint_as_float(hiw << 16);
    float h1 = __uint_as_float(hiw & 0xffff0000u);
    return pack_bf16(lo - h0, hi - h1);
}
__device__ __forceinline__ void mma_bf16(float* c,
                                         unsigned a0, unsigned a1, unsigned a2, unsigned a3,
                                         unsigned b0, unsigned b1) {
    asm("mma.sync.aligned.m16n8k16.row.col.f32.bf16.bf16.f32 "
        "{%0,%1,%2,%3},{%4,%5,%6,%7},{%8,%9},{%0,%1,%2,%3};"
        : "+f"(c[0]), "+f"(c[1]), "+f"(c[2]), "+f"(c[3])
        : "r"(a0), "r"(a1), "r"(a2), "r"(a3), "r"(b0), "r"(b1));
}

// ================= bf16-split tensor-core GEMM =================
// C[M,N] = A[M,K] @ W[N,K]^T (+bias, epilogue), 3-pass bf16 hi/lo split.
// BM=128, BN=64, BK=16; 8 warps 4(m)x2(n); warp tile 32x32 (2 m-frags x 4 n-frags).
// smem layout: [k-word 0..7][m or n], k-word = packed bf16 pair (k=2w, 2w+1).
// MODE 0: +bias   MODE 1: +bias+res   MODE 2: gelu(+bias)
#define AST 136   // 136 % 32 == 8 -> frag LDS bank = 8*tg + g, conflict-free
#define BST 72    // 72  % 32 == 8
template <int MODE>
__global__ __launch_bounds__(256, 3)
void gemm_bf16_kernel(const float* __restrict__ A, const float* __restrict__ W,
                      const float* __restrict__ bias, const float* __restrict__ res,
                      float* __restrict__ C, int M, int N, int K) {
    __shared__ unsigned AsHi[8 * AST], AsLo[8 * AST];
    __shared__ unsigned BsHi[8 * BST], BsLo[8 * BST];

    const int tid  = threadIdx.x;
    const int lane = tid & 31;
    const int wid  = tid >> 5;
    const int g    = lane >> 2;        // 0..7
    const int tg   = lane & 3;         // 0..3
    const int wm   = (wid & 3) * 32;
    const int wn   = (wid >> 2) * 32;

    const int m0 = blockIdx.y * 128, n0 = blockIdx.x * 64;

    float acc[2][4][4];
#pragma unroll
    for (int i = 0; i < 2; i++)
#pragma unroll
        for (int j = 0; j < 4; j++)
#pragma unroll
            for (int t = 0; t < 4; t++) acc[i][j][t] = 0.f;

    for (int k0 = 0; k0 < K; k0 += 16) {
        // ---- stage A tile 128x16 -> packed bf16 hi/lo (512 float4 / 256 thr) ----
#pragma unroll
        for (int j = 0; j < 2; j++) {
            int idx = j * 256 + tid;
            int r = idx >> 2, c4 = (idx & 3) * 4;
            float4 v = *reinterpret_cast<const float4*>(A + (size_t)(m0 + r) * K + k0 + c4);
            unsigned h0 = pack_bf16(v.x, v.y);
            unsigned h1 = pack_bf16(v.z, v.w);
            int kw = c4 >> 1;
            AsHi[kw * AST + r]       = h0;
            AsHi[(kw + 1) * AST + r] = h1;
            AsLo[kw * AST + r]       = lo_residual(h0, v.x, v.y);
            AsLo[(kw + 1) * AST + r] = lo_residual(h1, v.z, v.w);
        }
        // ---- stage B tile 64x16 (256 float4 / 256 thr) ----
        {
            int r = tid >> 2, c4 = (tid & 3) * 4;
            float4 v = *reinterpret_cast<const float4*>(W + (size_t)(n0 + r) * K + k0 + c4);
            unsigned h0 = pack_bf16(v.x, v.y);
            unsigned h1 = pack_bf16(v.z, v.w);
            int kw = c4 >> 1;
            BsHi[kw * BST + r]       = h0;
            BsHi[(kw + 1) * BST + r] = h1;
            BsLo[kw * BST + r]       = lo_residual(h0, v.x, v.y);
            BsLo[(kw + 1) * BST + r] = lo_residual(h1, v.z, v.w);
        }
        __syncthreads();

        // ---- B fragments (shared across m-frags) ----
        unsigned bH[4][2], bL[4][2];
#pragma unroll
        for (int nf = 0; nf < 4; nf++) {
            int nb = wn + nf * 8 + g;
            bH[nf][0] = BsHi[tg * BST + nb];
            bH[nf][1] = BsHi[(tg + 4) * BST + nb];
            bL[nf][0] = BsLo[tg * BST + nb];
            bL[nf][1] = BsLo[(tg + 4) * BST + nb];
        }
#pragma unroll
        for (int mf = 0; mf < 2; mf++) {
            int mb = wm + mf * 16 + g;
            unsigned aH0 = AsHi[tg * AST + mb];
            unsigned aH1 = AsHi[tg * AST + mb + 8];
            unsigned aH2 = AsHi[(tg + 4) * AST + mb];
            unsigned aH3 = AsHi[(tg + 4) * AST + mb + 8];
            unsigned aL0 = AsLo[tg * AST + mb];
            unsigned aL1 = AsLo[tg * AST + mb + 8];
            unsigned aL2 = AsLo[(tg + 4) * AST + mb];
            unsigned aL3 = AsLo[(tg + 4) * AST + mb + 8];
#pragma unroll
            for (int nf = 0; nf < 4; nf++) {
                mma_bf16(acc[mf][nf], aH0, aH1, aH2, aH3, bH[nf][0], bH[nf][1]);
                mma_bf16(acc[mf][nf], aH0, aH1, aH2, aH3, bL[nf][0], bL[nf][1]);
                mma_bf16(acc[mf][nf], aL0, aL1, aL2, aL3, bH[nf][0], bH[nf][1]);
            }
        }
        __syncthreads();
    }

    // ---- epilogue ----
#pragma unroll
    for (int mf = 0; mf < 2; mf++) {
        int r = m0 + wm + mf * 16 + g;
#pragma unroll
        for (int nf = 0; nf < 4; nf++) {
            int c = n0 + wn + nf * 8 + tg * 2;
#pragma unroll
            for (int half = 0; half < 2; half++) {
                int rr = r + half * 8;
#pragma unroll
                for (int cc = 0; cc < 2; cc++) {
                    float v = acc[mf][nf][half * 2 + cc] + bias[c + cc];
                    if (MODE == 1) v += res[(size_t)rr * N + c + cc];
                    if (MODE == 2) v = 0.5f * v * (1.0f + erff(v * 0.7071067811865476f));
                    C[(size_t)rr * N + c + cc] = v;
                }
            }
        }
    }
}

// ================= flash attention with bf16-split mma (unchanged R3) =================
#define KQ_STRIDE 20
#define V_STRIDE  69
#define OFF_KH 0
#define OFF_KL 2560
#define OFF_QH 5120
#define OFF_QL 7680
#define OFF_VH 10240
#define OFF_VL 12448
#define OFF_REL 14656
#define OFF_MSK 14721
#define SMEM_ATT_WORDS 15240
#define SMEM_ATT_BYTES (SMEM_ATT_WORDS*4)

__global__ __launch_bounds__(256, 1)
void attn_mma_kernel(const float* __restrict__ qkv, const float* __restrict__ bppm,
                     const float* __restrict__ pair_w, const float* __restrict__ pair_b,
                     const float* __restrict__ relpos_w, const float* __restrict__ relpos_b,
                     float* __restrict__ o) {
    extern __shared__ unsigned sm[];
    unsigned* KsHi = sm + OFF_KH;
    unsigned* KsLo = sm + OFF_KL;
    unsigned* QsHi = sm + OFF_QH;
    unsigned* QsLo = sm + OFF_QL;
    unsigned* VsHi = sm + OFF_VH;
    unsigned* VsLo = sm + OFF_VL;
    float*    rel  = (float*)(sm + OFF_REL);
    float*    msk  = (float*)(sm + OFF_MSK);

    const int tid  = threadIdx.x;
    const int lane = tid & 31;
    const int w    = tid >> 5;
    const int qt   = blockIdx.x;
    const int h    = blockIdx.y;
    const int b    = blockIdx.z;
    const int q0   = qt * 128;
    const int wq   = w * 16;

    const int g    = lane >> 2;
    const int tg   = lane & 3;

#pragma unroll
    for (int j = 0; j < 4; j++) {
        int r  = w * 16 + j * 4 + (lane >> 3);
        int c4 = (lane & 7) * 4;
        float4 v = *reinterpret_cast<const float4*>(
            qkv + (size_t)(b * LL + q0 + r) * QKVN + h * DHH + c4);
        unsigned h0 = pack_bf16(v.x, v.y);
        unsigned h1 = pack_bf16(v.z, v.w);
        int base = r * KQ_STRIDE + (c4 >> 1);
        QsHi[base]     = h0;
        QsHi[base + 1] = h1;
        QsLo[base]     = lo_residual(h0, v.x, v.y);
        QsLo[base + 1] = lo_residual(h1, v.z, v.w);
    }
    if (tid < BINS) rel[tid] = relpos_w[h * BINS + tid];
    for (int k = tid; k < LL; k += 256) msk[k] = g_maskf[b * LL + k];
    __syncthreads();

    const float pw    = pair_w[h];
    const float addc  = pair_b[h] + relpos_b[h];
    const float scale = 0.17677669529663687f;

    float m0v = -1e30f, m1v = -1e30f;
    float lp0 = 0.f,   lp1 = 0.f;
    float Oacc[4][4];
#pragma unroll
    for (int i = 0; i < 4; i++)
#pragma unroll
        for (int j = 0; j < 4; j++) Oacc[i][j] = 0.f;

    const int row0 = q0 + wq + g;

    for (int kt = 0; kt < 4; kt++) {
        const int k0 = kt * 128;

#pragma unroll
        for (int j = 0; j < 4; j++) {
            int r  = w * 16 + j * 4 + (lane >> 3);
            int c4 = (lane & 7) * 4;
            float4 v = *reinterpret_cast<const float4*>(
                qkv + (size_t)(b * LL + k0 + r) * QKVN + DDIM + h * DHH + c4);
            unsigned h0 = pack_bf16(v.x, v.y);
            unsigned h1 = pack_bf16(v.z, v.w);
            int base = r * KQ_STRIDE + (c4 >> 1);
            KsHi[base]     = h0;
            KsHi[base + 1] = h1;
            KsLo[base]     = lo_residual(h0, v.x, v.y);
            KsLo[base + 1] = lo_residual(h1, v.z, v.w);
        }
#pragma unroll
        for (int j = 0; j < 2; j++) {
            int p  = w * 8 + j * 4 + (lane >> 3);
            int d4 = (lane & 7) * 4;
            const float* base = qkv + (size_t)(b * LL + k0 + 2 * p) * QKVN + 2 * DDIM + h * DHH + d4;
            float4 v0 = *reinterpret_cast<const float4*>(base);
            float4 v1 = *reinterpret_cast<const float4*>(base + QKVN);
            float a0[4] = {v0.x, v0.y, v0.z, v0.w};
            float a1[4] = {v1.x, v1.y, v1.z, v1.w};
#pragma unroll
            for (int i = 0; i < 4; i++) {
                unsigned hw = pack_bf16(a0[i], a1[i]);
                VsHi[(d4 + i) * V_STRIDE + p] = hw;
                VsLo[(d4 + i) * V_STRIDE + p] = lo_residual(hw, a0[i], a1[i]);
            }
        }
        __syncthreads();

        float S[16][4];
#pragma unroll
        for (int nt = 0; nt < 16; nt++)
#pragma unroll
            for (int c = 0; c < 4; c++) S[nt][c] = 0.f;

#pragma unroll
        for (int ks = 0; ks < 2; ks++) {
            int ab = (wq + g) * KQ_STRIDE + ks * 8 + tg;
            unsigned aH0 = QsHi[ab],              aH1 = QsHi[ab + 8 * KQ_STRIDE];
            unsigned aH2 = QsHi[ab + 4],          aH3 = QsHi[ab + 8 * KQ_STRIDE + 4];
            unsigned aL0 = QsLo[ab],              aL1 = QsLo[ab + 8 * KQ_STRIDE];
            unsigned aL2 = QsLo[ab + 4],          aL3 = QsLo[ab + 8 * KQ_STRIDE + 4];
#pragma unroll
            for (int nt = 0; nt < 16; nt++) {
                int bb = (nt * 8 + g) * KQ_STRIDE + ks * 8 + tg;
                unsigned bH0 = KsHi[bb], bH1 = KsHi[bb + 4];
                unsigned bL0 = KsLo[bb], bL1 = KsLo[bb + 4];
                mma_bf16(S[nt], aH0, aH1, aH2, aH3, bH0, bH1);
                mma_bf16(S[nt], aH0, aH1, aH2, aH3, bL0, bL1);
                mma_bf16(S[nt], aL0, aL1, aL2, aL3, bH0, bH1);
            }
        }

#pragma unroll
        for (int nt = 0; nt < 16; nt++) {
            int col = k0 + nt * 8 + tg * 2;
            float2 bp0 = *reinterpret_cast<const float2*>(
                bppm + ((size_t)(b * LL + row0)) * LL + col);
            float2 bp1 = *reinterpret_cast<const float2*>(
                bppm + ((size_t)(b * LL + row0 + 8)) * LL + col);
            int d00 = min(KCLIP, max(-KCLIP, row0 - col))     + KCLIP;
            int d01 = min(KCLIP, max(-KCLIP, row0 - col - 1)) + KCLIP;
            int d10 = min(KCLIP, max(-KCLIP, row0 + 8 - col))     + KCLIP;
            int d11 = min(KCLIP, max(-KCLIP, row0 + 8 - col - 1)) + KCLIP;
            float mk0 = msk[col], mk1 = msk[col + 1];
            float s0 = S[nt][0] * scale + bp0.x * pw + rel[d00] + addc;
            float s1 = S[nt][1] * scale + bp0.y * pw + rel[d01] + addc;
            float s2 = S[nt][2] * scale + bp1.x * pw + rel[d10] + addc;
            float s3 = S[nt][3] * scale + bp1.y * pw + rel[d11] + addc;
            S[nt][0] = (mk0 != 0.f) ? s0 : -1e9f;
            S[nt][1] = (mk1 != 0.f) ? s1 : -1e9f;
            S[nt][2] = (mk0 != 0.f) ? s2 : -1e9f;
            S[nt][3] = (mk1 != 0.f) ? s3 : -1e9f;
        }

        float t0 = -1e30f, t1 = -1e30f;
#pragma unroll
        for (int nt = 0; nt < 16; nt++) {
            t0 = fmaxf(t0, fmaxf(S[nt][0], S[nt][1]));
            t1 = fmaxf(t1, fmaxf(S[nt][2], S[nt][3]));
        }
        t0 = fmaxf(t0, __shfl_xor_sync(0xffffffffu, t0, 1));
        t0 = fmaxf(t0, __shfl_xor_sync(0xffffffffu, t0, 2));
        t1 = fmaxf(t1, __shfl_xor_sync(0xffffffffu, t1, 1));
        t1 = fmaxf(t1, __shfl_xor_sync(0xffffffffu, t1, 2));

        float mn0 = fmaxf(m0v, t0), mn1 = fmaxf(m1v, t1);
        float al0 = __expf(m0v - mn0), al1 = __expf(m1v - mn1);
        m0v = mn0; m1v = mn1;

        float sum0 = 0.f, sum1 = 0.f;
#pragma unroll
        for (int nt = 0; nt < 16; nt++) {
            S[nt][0] = __expf(S[nt][0] - m0v);
            S[nt][1] = __expf(S[nt][1] - m0v);
            S[nt][2] = __expf(S[nt][2] - m1v);
            S[nt][3] = __expf(S[nt][3] - m1v);
            sum0 += S[nt][0] + S[nt][1];
            sum1 += S[nt][2] + S[nt][3];
        }
        lp0 = lp0 * al0 + sum0;
        lp1 = lp1 * al1 + sum1;
#pragma unroll
        for (int nt = 0; nt < 4; nt++) {
            Oacc[nt][0] *= al0; Oacc[nt][1] *= al0;
            Oacc[nt][2] *= al1; Oacc[nt][3] *= al1;
        }

#pragma unroll
        for (int j = 0; j < 8; j++) {
            unsigned pH0 = pack_bf16(S[2*j][0],   S[2*j][1]);
            unsigned pH1 = pack_bf16(S[2*j][2],   S[2*j][3]);
            unsigned pH2 = pack_bf16(S[2*j+1][0], S[2*j+1][1]);
            unsigned pH3 = pack_bf16(S[2*j+1][2], S[2*j+1][3]);
            unsigned pL0 = lo_residual(pH0, S[2*j][0],   S[2*j][1]);
            unsigned pL1 = lo_residual(pH1, S[2*j][2],   S[2*j][3]);
            unsigned pL2 = lo_residual(pH2, S[2*j+1][0], S[2*j+1][1]);
            unsigned pL3 = lo_residual(pH3, S[2*j+1][2], S[2*j+1][3]);
#pragma unroll
            for (int nt = 0; nt < 4; nt++) {
                int bb = (nt * 8 + g) * V_STRIDE + j * 8 + tg;
                unsigned bH0 = VsHi[bb], bH1 = VsHi[bb + 4];
                unsigned bL0 = VsLo[bb], bL1 = VsLo[bb + 4];
                mma_bf16(Oacc[nt], pH0, pH1, pH2, pH3, bH0, bH1);
                mma_bf16(Oacc[nt], pH0, pH1, pH2, pH3, bL0, bL1);
                mma_bf16(Oacc[nt], pL0, pL1, pL2, pL3, bH0, bH1);
            }
        }
        __syncthreads();
    }

    float l0 = lp0 + __shfl_xor_sync(0xffffffffu, lp0, 1);
    l0 += __shfl_xor_sync(0xffffffffu, l0, 2);
    float l1 = lp1 + __shfl_xor_sync(0xffffffffu, lp1, 1);
    l1 += __shfl_xor_sync(0xffffffffu, l1, 2);
    float inv0 = 1.0f / l0, inv1 = 1.0f / l1;

#pragma unroll
    for (int nt = 0; nt < 4; nt++) {
        int d = h * DHH + nt * 8 + tg * 2;
        float2 o0 = make_float2(Oacc[nt][0] * inv0, Oacc[nt][1] * inv0);
        float2 o1 = make_float2(Oacc[nt][2] * inv1, Oacc[nt][3] * inv1);
        *reinterpret_cast<float2*>(o + ((size_t)(b * LL + row0))     * DDIM + d) = o0;
        *reinterpret_cast<float2*>(o + ((size_t)(b * LL + row0 + 8)) * DDIM + d) = o1;
    }
}

// ---------------- final projection ----------------
__global__ void proj_kernel(const float* __restrict__ x,
                            const float* __restrict__ pw,
                            const float* __restrict__ pb,
                            float* __restrict__ out) {
    int row  = blockIdx.x * 8 + (threadIdx.x >> 5);
    int lane = threadIdx.x & 31;
    const float* xr = x + (size_t)row * DDIM;
    float d0 = 0.f, d1 = 0.f;
#pragma unroll
    for (int j = 0; j < 6; j++) {
        int c = lane + 32*j;
        float v = xr[c];
        d0 += v * pw[c];
        d1 += v * pw[DDIM + c];
    }
#pragma unroll
    for (int o = 16; o; o >>= 1) {
        d0 += __shfl_xor_sync(0xffffffffu, d0, o);
        d1 += __shfl_xor_sync(0xffffffffu, d1, o);
    }
    if (lane == 0) {
        out[row*2 + 0] = d0 + pb[0];
        out[row*2 + 1] = d1 + pb[1];
    }
}

// ---------------- launch ----------------
extern "C" void kernel_launch(void* const* d_in, const int* in_sizes, int n_in,
                              void* d_out, int out_size) {
    const int*   seq      = (const int*)  d_in[0];
    const void*  mask     =               d_in[1];
    const float* bppm     = (const float*)d_in[2];
    const float* emb      = (const float*)d_in[3];
    const float* pair_w   = (const float*)d_in[4];
    const float* pair_b   = (const float*)d_in[5];
    const float* relpos_w = (const float*)d_in[6];
    const float* relpos_b = (const float*)d_in[7];
    const float* ln1_s    = (const float*)d_in[8];
    const float* ln1_b    = (const float*)d_in[9];
    const float* qkv_w    = (const float*)d_in[10];
    const float* qkv_b    = (const float*)d_in[11];
    const float* out_w    = (const float*)d_in[12];
    const float* out_b    = (const float*)d_in[13];
    const float* ln2_s    = (const float*)d_in[14];
    const float* ln2_b    = (const float*)d_in[15];
    const float* ff1_w    = (const float*)d_in[16];
    const float* ff1_b    = (const float*)d_in[17];
    const float* ff2_w    = (const float*)d_in[18];
    const float* ff2_b    = (const float*)d_in[19];
    const float* proj_w   = (const float*)d_in[20];
    const float* proj_b   = (const float*)d_in[21];
    float* out = (float*)d_out;

    float *x, *h, *qkvB, *o, *ff;
    cudaGetSymbolAddress((void**)&x,    g_x);
    cudaGetSymbolAddress((void**)&h,    g_h);
    cudaGetSymbolAddress((void**)&qkvB, g_qkv);
    cudaGetSymbolAddress((void**)&o,    g_o);
    cudaGetSymbolAddress((void**)&ff,   g_ff);

    static int attr_set = 0;
    if (!attr_set) {
        cudaFuncSetAttribute(attn_mma_kernel,
                             cudaFuncAttributeMaxDynamicSharedMemorySize, SMEM_ATT_BYTES);
        attr_set = 1;
    }

    mask_reset_kernel<<<1, 1>>>();
    mask_detect_kernel<<<(NROW + 255) / 256, 256>>>((const unsigned char*)mask);
    mask_expand_kernel<<<(NROW + 255) / 256, 256>>>(mask);

    embed_kernel<<<(NROW * DDIM) / 256, 256>>>(seq, emb, x);

    dim3 gQKV(QKVN / 64, NROW / 128);
    dim3 gOUT(DDIM / 64, NROW / 128);
    dim3 gFF1(FFN  / 64, NROW / 128);
    dim3 gATT(LL / 128, HH, BB);

    for (int i = 0; i < DEPTH; i++) {
        ln_kernel<<<NROW / 8, 256>>>(x, ln1_s + i*DDIM, ln1_b + i*DDIM, h);
        gemm_bf16_kernel<0><<<gQKV, 256>>>(h, qkv_w + (size_t)i*QKVN*DDIM,
                                           qkv_b + i*QKVN, nullptr, qkvB,
                                           NROW, QKVN, DDIM);
        attn_mma_kernel<<<gATT, 256, SMEM_ATT_BYTES>>>(qkvB, bppm, pair_w, pair_b,
                                                       relpos_w, relpos_b, o);
        gemm_bf16_kernel<1><<<gOUT, 256>>>(o, out_w + (size_t)i*DDIM*DDIM,
                                           out_b + i*DDIM, x, x,
                                           NROW, DDIM, DDIM);
        ln_kernel<<<NROW / 8, 256>>>(x, ln2_s + i*DDIM, ln2_b + i*DDIM, h);
        gemm_bf16_kernel<2><<<gFF1, 256>>>(h, ff1_w + (size_t)i*FFN*DDIM,
                                           ff1_b + i*FFN, nullptr, ff,
                                           NROW, FFN, DDIM);
        gemm_bf16_kernel<1><<<gOUT, 256>>>(ff, ff2_w + (size_t)i*DDIM*FFN,
                                           ff2_b + i*DDIM, x, x,
                                           NROW, DDIM, FFN);
    }

    proj_kernel<<<NROW / 8, 256>>>(x, proj_w, proj_b, out);
}

// round 5
// speedup vs baseline: 6.0159x; 1.0030x over previous
#include <cuda_runtime.h>
#include <cuda_bf16.h>
#include <math.h>

// ---------------- problem constants ----------------
#define BB   32
#define LL   512
#define DDIM 192
#define DEPTH 12
#define HH   6
#define DHH  32
#define KCLIP 32
#define BINS 65
#define NROW (BB*LL)          // 16384
#define QKVN (3*DDIM)         // 576
#define FFN  (4*DDIM)         // 768

// ---------------- scratch (static device arrays; no allocation) ----------------
__device__ float g_x  [NROW*DDIM];
__device__ float g_h  [NROW*DDIM];
__device__ float g_qkv[NROW*QKVN];
__device__ float g_o  [NROW*DDIM];
__device__ float g_ff [NROW*FFN];
__device__ float g_maskf[NROW];
__device__ int   g_mask_is_u8;

// ---------------- mask dtype detection ----------------
__global__ void mask_reset_kernel() { g_mask_is_u8 = 0; }

__global__ void mask_detect_kernel(const unsigned char* __restrict__ m) {
    int i = blockIdx.x * 256 + threadIdx.x;
    if (i < NROW && (i & 3) != 0 && m[i] != 0) atomicOr(&g_mask_is_u8, 1);
}

__global__ void mask_expand_kernel(const void* __restrict__ m) {
    int i = blockIdx.x * 256 + threadIdx.x;
    if (i >= NROW) return;
    int v;
    if (g_mask_is_u8) v = ((const unsigned char*)m)[i];
    else              v = ((const int*)m)[i];
    g_maskf[i] = v ? 1.0f : 0.0f;
}

// ---------------- embedding ----------------
__global__ void embed_kernel(const int* __restrict__ seq,
                             const float* __restrict__ emb,
                             float* __restrict__ x) {
    int i = blockIdx.x * 256 + threadIdx.x;
    if (i >= NROW * DDIM) return;
    int row = i / DDIM, c = i - row * DDIM;
    x[i] = emb[seq[row] * DDIM + c];
}

// ---------------- layernorm (warp per row) ----------------
__global__ void ln_kernel(const float* __restrict__ x,
                          const float* __restrict__ s,
                          const float* __restrict__ b,
                          float* __restrict__ out) {
    int row  = blockIdx.x * 8 + (threadIdx.x >> 5);
    int lane = threadIdx.x & 31;
    const float* xr = x + (size_t)row * DDIM;
    float v[6], sum = 0.f;
#pragma unroll
    for (int j = 0; j < 6; j++) { v[j] = xr[lane + 32*j]; sum += v[j]; }
#pragma unroll
    for (int o = 16; o; o >>= 1) sum += __shfl_xor_sync(0xffffffffu, sum, o);
    float mu = sum * (1.0f / DDIM);
    float vs = 0.f;
#pragma unroll
    for (int j = 0; j < 6; j++) { float d = v[j] - mu; vs += d * d; }
#pragma unroll
    for (int o = 16; o; o >>= 1) vs += __shfl_xor_sync(0xffffffffu, vs, o);
    float inv = rsqrtf(vs * (1.0f / DDIM) + 1e-5f);
    float* orow = out + (size_t)row * DDIM;
#pragma unroll
    for (int j = 0; j < 6; j++) {
        int c = lane + 32*j;
        orow[c] = (v[j] - mu) * inv * s[c] + b[c];
    }
}

// ---------------- bf16 helpers ----------------
__device__ __forceinline__ unsigned pack_bf16(float lo, float hi) {
    unsigned r;
    asm("cvt.rn.bf16x2.f32 %0, %1, %2;" : "=r"(r) : "f"(hi), "f"(lo));
    return r;
}
__device__ __forceinline__ unsigned lo_residual(unsigned hiw, float lo, float hi) {
    float h0 = __uint_as_float(hiw << 16);
    float h1 = __uint_as_float(hiw & 0xffff0000u);
    return pack_bf16(lo - h0, hi - h1);
}
__device__ __forceinline__ void mma_bf16(float* c,
                                         unsigned a0, unsigned a1, unsigned a2, unsigned a3,
                                         unsigned b0, unsigned b1) {
    asm("mma.sync.aligned.m16n8k16.row.col.f32.bf16.bf16.f32 "
        "{%0,%1,%2,%3},{%4,%5,%6,%7},{%8,%9},{%0,%1,%2,%3};"
        : "+f"(c[0]), "+f"(c[1]), "+f"(c[2]), "+f"(c[3])
        : "r"(a0), "r"(a1), "r"(a2), "r"(a3), "r"(b0), "r"(b1));
}

// ================= bf16-split tensor-core GEMM (register-prefetch pipeline) ==========
// C[M,N] = A[M,K] @ W[N,K]^T (+bias, epilogue), 3-pass bf16 hi/lo split.
// BM=128, BN=64, BK=16; 8 warps 4(m)x2(n); warp tile 32x32.
// k-loop: store prefetched regs -> sync -> issue next LDGs -> mma (covers latency) -> sync
#define AST 136   // 136 % 32 == 8 -> frag LDS conflict-free
#define BST 72
template <int MODE>
__global__ __launch_bounds__(256, 2)
void gemm_bf16_kernel(const float* __restrict__ A, const float* __restrict__ W,
                      const float* __restrict__ bias, const float* __restrict__ res,
                      float* __restrict__ C, int M, int N, int K) {
    __shared__ unsigned AsHi[8 * AST], AsLo[8 * AST];
    __shared__ unsigned BsHi[8 * BST], BsLo[8 * BST];

    const int tid  = threadIdx.x;
    const int lane = tid & 31;
    const int wid  = tid >> 5;
    const int g    = lane >> 2;
    const int tg   = lane & 3;
    const int wm   = (wid & 3) * 32;
    const int wn   = (wid >> 2) * 32;

    const int m0 = blockIdx.y * 128, n0 = blockIdx.x * 64;

    // this thread's staging slots
    const int ar0 = tid >> 1,           ac0 = (tid & 1) * 8;       // A: rows ar0, cols ac0..ac0+7 (2 float4)
    const int br  = tid >> 2,           bc4 = (tid & 3) * 4;       // B: 1 float4

    const float* Aptr = A + (size_t)(m0 + ar0) * K + ac0;
    const float* Wptr = W + (size_t)(n0 + br)  * K + bc4;

    float4 pa0 = *reinterpret_cast<const float4*>(Aptr);
    float4 pa1 = *reinterpret_cast<const float4*>(Aptr + 4);
    float4 pb  = *reinterpret_cast<const float4*>(Wptr);

    float acc[2][4][4];
#pragma unroll
    for (int i = 0; i < 2; i++)
#pragma unroll
        for (int j = 0; j < 4; j++)
#pragma unroll
            for (int t = 0; t < 4; t++) acc[i][j][t] = 0.f;

    for (int k0 = 0; k0 < K; k0 += 16) {
        // ---- store prefetched tile to smem (packed bf16 hi/lo) ----
        {
            int kw = ac0 >> 1;
            unsigned h0 = pack_bf16(pa0.x, pa0.y);
            unsigned h1 = pack_bf16(pa0.z, pa0.w);
            unsigned h2 = pack_bf16(pa1.x, pa1.y);
            unsigned h3 = pack_bf16(pa1.z, pa1.w);
            AsHi[(kw + 0) * AST + ar0] = h0;
            AsHi[(kw + 1) * AST + ar0] = h1;
            AsHi[(kw + 2) * AST + ar0] = h2;
            AsHi[(kw + 3) * AST + ar0] = h3;
            AsLo[(kw + 0) * AST + ar0] = lo_residual(h0, pa0.x, pa0.y);
            AsLo[(kw + 1) * AST + ar0] = lo_residual(h1, pa0.z, pa0.w);
            AsLo[(kw + 2) * AST + ar0] = lo_residual(h2, pa1.x, pa1.y);
            AsLo[(kw + 3) * AST + ar0] = lo_residual(h3, pa1.z, pa1.w);

            int kwb = bc4 >> 1;
            unsigned b0 = pack_bf16(pb.x, pb.y);
            unsigned b1 = pack_bf16(pb.z, pb.w);
            BsHi[(kwb + 0) * BST + br] = b0;
            BsHi[(kwb + 1) * BST + br] = b1;
            BsLo[(kwb + 0) * BST + br] = lo_residual(b0, pb.x, pb.y);
            BsLo[(kwb + 1) * BST + br] = lo_residual(b1, pb.z, pb.w);
        }
        __syncthreads();

        // ---- issue next tile's loads (latency covered by mma below) ----
        if (k0 + 16 < K) {
            Aptr += 16; Wptr += 16;
            pa0 = *reinterpret_cast<const float4*>(Aptr);
            pa1 = *reinterpret_cast<const float4*>(Aptr + 4);
            pb  = *reinterpret_cast<const float4*>(Wptr);
        }

        // ---- fragments + mma ----
        unsigned bH[4][2], bL[4][2];
#pragma unroll
        for (int nf = 0; nf < 4; nf++) {
            int nb = wn + nf * 8 + g;
            bH[nf][0] = BsHi[tg * BST + nb];
            bH[nf][1] = BsHi[(tg + 4) * BST + nb];
            bL[nf][0] = BsLo[tg * BST + nb];
            bL[nf][1] = BsLo[(tg + 4) * BST + nb];
        }
#pragma unroll
        for (int mf = 0; mf < 2; mf++) {
            int mb = wm + mf * 16 + g;
            unsigned aH0 = AsHi[tg * AST + mb];
            unsigned aH1 = AsHi[tg * AST + mb + 8];
            unsigned aH2 = AsHi[(tg + 4) * AST + mb];
            unsigned aH3 = AsHi[(tg + 4) * AST + mb + 8];
            unsigned aL0 = AsLo[tg * AST + mb];
            unsigned aL1 = AsLo[tg * AST + mb + 8];
            unsigned aL2 = AsLo[(tg + 4) * AST + mb];
            unsigned aL3 = AsLo[(tg + 4) * AST + mb + 8];
#pragma unroll
            for (int nf = 0; nf < 4; nf++) {
                mma_bf16(acc[mf][nf], aH0, aH1, aH2, aH3, bH[nf][0], bH[nf][1]);
                mma_bf16(acc[mf][nf], aH0, aH1, aH2, aH3, bL[nf][0], bL[nf][1]);
                mma_bf16(acc[mf][nf], aL0, aL1, aL2, aL3, bH[nf][0], bH[nf][1]);
            }
        }
        __syncthreads();
    }

    // ---- epilogue ----
#pragma unroll
    for (int mf = 0; mf < 2; mf++) {
        int r = m0 + wm + mf * 16 + g;
#pragma unroll
        for (int nf = 0; nf < 4; nf++) {
            int c = n0 + wn + nf * 8 + tg * 2;
#pragma unroll
            for (int half = 0; half < 2; half++) {
                int rr = r + half * 8;
#pragma unroll
                for (int cc = 0; cc < 2; cc++) {
                    float v = acc[mf][nf][half * 2 + cc] + bias[c + cc];
                    if (MODE == 1) v += res[(size_t)rr * N + c + cc];
                    if (MODE == 2) v = 0.5f * v * (1.0f + erff(v * 0.7071067811865476f));
                    C[(size_t)rr * N + c + cc] = v;
                }
            }
        }
    }
}

// ================= flash attention with bf16-split mma =================
#define KQ_STRIDE 20
#define V_STRIDE  69
#define OFF_KH 0
#define OFF_KL 2560
#define OFF_QH 5120
#define OFF_QL 7680
#define OFF_VH 10240
#define OFF_VL 12448
#define OFF_REL 14656
#define OFF_MSK 14721
#define SMEM_ATT_WORDS 15240
#define SMEM_ATT_BYTES (SMEM_ATT_WORDS*4)

__global__ __launch_bounds__(256, 2)
void attn_mma_kernel(const float* __restrict__ qkv, const float* __restrict__ bppm,
                     const float* __restrict__ pair_w, const float* __restrict__ pair_b,
                     const float* __restrict__ relpos_w, const float* __restrict__ relpos_b,
                     float* __restrict__ o) {
    extern __shared__ unsigned sm[];
    unsigned* KsHi = sm + OFF_KH;
    unsigned* KsLo = sm + OFF_KL;
    unsigned* QsHi = sm + OFF_QH;
    unsigned* QsLo = sm + OFF_QL;
    unsigned* VsHi = sm + OFF_VH;
    unsigned* VsLo = sm + OFF_VL;
    float*    rel  = (float*)(sm + OFF_REL);
    float*    msk  = (float*)(sm + OFF_MSK);

    const int tid  = threadIdx.x;
    const int lane = tid & 31;
    const int w    = tid >> 5;
    const int qt   = blockIdx.x;
    const int h    = blockIdx.y;
    const int b    = blockIdx.z;
    const int q0   = qt * 128;
    const int wq   = w * 16;

    const int g    = lane >> 2;
    const int tg   = lane & 3;

#pragma unroll
    for (int j = 0; j < 4; j++) {
        int r  = w * 16 + j * 4 + (lane >> 3);
        int c4 = (lane & 7) * 4;
        float4 v = *reinterpret_cast<const float4*>(
            qkv + (size_t)(b * LL + q0 + r) * QKVN + h * DHH + c4);
        unsigned h0 = pack_bf16(v.x, v.y);
        unsigned h1 = pack_bf16(v.z, v.w);
        int base = r * KQ_STRIDE + (c4 >> 1);
        QsHi[base]     = h0;
        QsHi[base + 1] = h1;
        QsLo[base]     = lo_residual(h0, v.x, v.y);
        QsLo[base + 1] = lo_residual(h1, v.z, v.w);
    }
    if (tid < BINS) rel[tid] = relpos_w[h * BINS + tid];
    for (int k = tid; k < LL; k += 256) msk[k] = g_maskf[b * LL + k];
    __syncthreads();

    const float pw    = pair_w[h];
    const float addc  = pair_b[h] + relpos_b[h];
    const float scale = 0.17677669529663687f;

    float m0v = -1e30f, m1v = -1e30f;
    float lp0 = 0.f,   lp1 = 0.f;
    float Oacc[4][4];
#pragma unroll
    for (int i = 0; i < 4; i++)
#pragma unroll
        for (int j = 0; j < 4; j++) Oacc[i][j] = 0.f;

    const int row0 = q0 + wq + g;

    for (int kt = 0; kt < 4; kt++) {
        const int k0 = kt * 128;

#pragma unroll
        for (int j = 0; j < 4; j++) {
            int r  = w * 16 + j * 4 + (lane >> 3);
            int c4 = (lane & 7) * 4;
            float4 v = *reinterpret_cast<const float4*>(
                qkv + (size_t)(b * LL + k0 + r) * QKVN + DDIM + h * DHH + c4);
            unsigned h0 = pack_bf16(v.x, v.y);
            unsigned h1 = pack_bf16(v.z, v.w);
            int base = r * KQ_STRIDE + (c4 >> 1);
            KsHi[base]     = h0;
            KsHi[base + 1] = h1;
            KsLo[base]     = lo_residual(h0, v.x, v.y);
            KsLo[base + 1] = lo_residual(h1, v.z, v.w);
        }
#pragma unroll
        for (int j = 0; j < 2; j++) {
            int p  = w * 8 + j * 4 + (lane >> 3);
            int d4 = (lane & 7) * 4;
            const float* base = qkv + (size_t)(b * LL + k0 + 2 * p) * QKVN + 2 * DDIM + h * DHH + d4;
            float4 v0 = *reinterpret_cast<const float4*>(base);
            float4 v1 = *reinterpret_cast<const float4*>(base + QKVN);
            float a0[4] = {v0.x, v0.y, v0.z, v0.w};
            float a1[4] = {v1.x, v1.y, v1.z, v1.w};
#pragma unroll
            for (int i = 0; i < 4; i++) {
                unsigned hw = pack_bf16(a0[i], a1[i]);
                VsHi[(d4 + i) * V_STRIDE + p] = hw;
                VsLo[(d4 + i) * V_STRIDE + p] = lo_residual(hw, a0[i], a1[i]);
            }
        }
        __syncthreads();

        float S[16][4];
#pragma unroll
        for (int nt = 0; nt < 16; nt++)
#pragma unroll
            for (int c = 0; c < 4; c++) S[nt][c] = 0.f;

#pragma unroll
        for (int ks = 0; ks < 2; ks++) {
            int ab = (wq + g) * KQ_STRIDE + ks * 8 + tg;
            unsigned aH0 = QsHi[ab],              aH1 = QsHi[ab + 8 * KQ_STRIDE];
            unsigned aH2 = QsHi[ab + 4],          aH3 = QsHi[ab + 8 * KQ_STRIDE + 4];
            unsigned aL0 = QsLo[ab],              aL1 = QsLo[ab + 8 * KQ_STRIDE];
            unsigned aL2 = QsLo[ab + 4],          aL3 = QsLo[ab + 8 * KQ_STRIDE + 4];
#pragma unroll
            for (int nt = 0; nt < 16; nt++) {
                int bb = (nt * 8 + g) * KQ_STRIDE + ks * 8 + tg;
                unsigned bH0 = KsHi[bb], bH1 = KsHi[bb + 4];
                unsigned bL0 = KsLo[bb], bL1 = KsLo[bb + 4];
                mma_bf16(S[nt], aH0, aH1, aH2, aH3, bH0, bH1);
                mma_bf16(S[nt], aH0, aH1, aH2, aH3, bL0, bL1);
                mma_bf16(S[nt], aL0, aL1, aL2, aL3, bH0, bH1);
            }
        }

#pragma unroll
        for (int nt = 0; nt < 16; nt++) {
            int col = k0 + nt * 8 + tg * 2;
            float2 bp0 = *reinterpret_cast<const float2*>(
                bppm + ((size_t)(b * LL + row0)) * LL + col);
            float2 bp1 = *reinterpret_cast<const float2*>(
                bppm + ((size_t)(b * LL + row0 + 8)) * LL + col);
            int d00 = min(KCLIP, max(-KCLIP, row0 - col))     + KCLIP;
            int d01 = min(KCLIP, max(-KCLIP, row0 - col - 1)) + KCLIP;
            int d10 = min(KCLIP, max(-KCLIP, row0 + 8 - col))     + KCLIP;
            int d11 = min(KCLIP, max(-KCLIP, row0 + 8 - col - 1)) + KCLIP;
            float mk0 = msk[col], mk1 = msk[col + 1];
            float s0 = S[nt][0] * scale + bp0.x * pw + rel[d00] + addc;
            float s1 = S[nt][1] * scale + bp0.y * pw + rel[d01] + addc;
            float s2 = S[nt][2] * scale + bp1.x * pw + rel[d10] + addc;
            float s3 = S[nt][3] * scale + bp1.y * pw + rel[d11] + addc;
            S[nt][0] = (mk0 != 0.f) ? s0 : -1e9f;
            S[nt][1] = (mk1 != 0.f) ? s1 : -1e9f;
            S[nt][2] = (mk0 != 0.f) ? s2 : -1e9f;
            S[nt][3] = (mk1 != 0.f) ? s3 : -1e9f;
        }

        float t0 = -1e30f, t1 = -1e30f;
#pragma unroll
        for (int nt = 0; nt < 16; nt++) {
            t0 = fmaxf(t0, fmaxf(S[nt][0], S[nt][1]));
            t1 = fmaxf(t1, fmaxf(S[nt][2], S[nt][3]));
        }
        t0 = fmaxf(t0, __shfl_xor_sync(0xffffffffu, t0, 1));
        t0 = fmaxf(t0, __shfl_xor_sync(0xffffffffu, t0, 2));
        t1 = fmaxf(t1, __shfl_xor_sync(0xffffffffu, t1, 1));
        t1 = fmaxf(t1, __shfl_xor_sync(0xffffffffu, t1, 2));

        float mn0 = fmaxf(m0v, t0), mn1 = fmaxf(m1v, t1);
        float al0 = __expf(m0v - mn0), al1 = __expf(m1v - mn1);
        m0v = mn0; m1v = mn1;

        float sum0 = 0.f, sum1 = 0.f;
#pragma unroll
        for (int nt = 0; nt < 16; nt++) {
            S[nt][0] = __expf(S[nt][0] - m0v);
            S[nt][1] = __expf(S[nt][1] - m0v);
            S[nt][2] = __expf(S[nt][2] - m1v);
            S[nt][3] = __expf(S[nt][3] - m1v);
            sum0 += S[nt][0] + S[nt][1];
            sum1 += S[nt][2] + S[nt][3];
        }
        lp0 = lp0 * al0 + sum0;
        lp1 = lp1 * al1 + sum1;
#pragma unroll
        for (int nt = 0; nt < 4; nt++) {
            Oacc[nt][0] *= al0; Oacc[nt][1] *= al0;
            Oacc[nt][2] *= al1; Oacc[nt][3] *= al1;
        }

#pragma unroll
        for (int j = 0; j < 8; j++) {
            unsigned pH0 = pack_bf16(S[2*j][0],   S[2*j][1]);
            unsigned pH1 = pack_bf16(S[2*j][2],   S[2*j][3]);
            unsigned pH2 = pack_bf16(S[2*j+1][0], S[2*j+1][1]);
            unsigned pH3 = pack_bf16(S[2*j+1][2], S[2*j+1][3]);
            unsigned pL0 = lo_residual(pH0, S[2*j][0],   S[2*j][1]);
            unsigned pL1 = lo_residual(pH1, S[2*j][2],   S[2*j][3]);
            unsigned pL2 = lo_residual(pH2, S[2*j+1][0], S[2*j+1][1]);
            unsigned pL3 = lo_residual(pH3, S[2*j+1][2], S[2*j+1][3]);
#pragma unroll
            for (int nt = 0; nt < 4; nt++) {
                int bb = (nt * 8 + g) * V_STRIDE + j * 8 + tg;
                unsigned bH0 = VsHi[bb], bH1 = VsHi[bb + 4];
                unsigned bL0 = VsLo[bb], bL1 = VsLo[bb + 4];
                mma_bf16(Oacc[nt], pH0, pH1, pH2, pH3, bH0, bH1);
                mma_bf16(Oacc[nt], pH0, pH1, pH2, pH3, bL0, bL1);
                mma_bf16(Oacc[nt], pL0, pL1, pL2, pL3, bH0, bH1);
            }
        }
        __syncthreads();
    }

    float l0 = lp0 + __shfl_xor_sync(0xffffffffu, lp0, 1);
    l0 += __shfl_xor_sync(0xffffffffu, l0, 2);
    float l1 = lp1 + __shfl_xor_sync(0xffffffffu, lp1, 1);
    l1 += __shfl_xor_sync(0xffffffffu, l1, 2);
    float inv0 = 1.0f / l0, inv1 = 1.0f / l1;

#pragma unroll
    for (int nt = 0; nt < 4; nt++) {
        int d = h * DHH + nt * 8 + tg * 2;
        float2 o0 = make_float2(Oacc[nt][0] * inv0, Oacc[nt][1] * inv0);
        float2 o1 = make_float2(Oacc[nt][2] * inv1, Oacc[nt][3] * inv1);
        *reinterpret_cast<float2*>(o + ((size_t)(b * LL + row0))     * DDIM + d) = o0;
        *reinterpret_cast<float2*>(o + ((size_t)(b * LL + row0 + 8)) * DDIM + d) = o1;
    }
}

// ---------------- final projection ----------------
__global__ void proj_kernel(const float* __restrict__ x,
                            const float* __restrict__ pw,
                            const float* __restrict__ pb,
                            float* __restrict__ out) {
    int row  = blockIdx.x * 8 + (threadIdx.x >> 5);
    int lane = threadIdx.x & 31;
    const float* xr = x + (size_t)row * DDIM;
    float d0 = 0.f, d1 = 0.f;
#pragma unroll
    for (int j = 0; j < 6; j++) {
        int c = lane + 32*j;
        float v = xr[c];
        d0 += v * pw[c];
        d1 += v * pw[DDIM + c];
    }
#pragma unroll
    for (int o = 16; o; o >>= 1) {
        d0 += __shfl_xor_sync(0xffffffffu, d0, o);
        d1 += __shfl_xor_sync(0xffffffffu, d1, o);
    }
    if (lane == 0) {
        out[row*2 + 0] = d0 + pb[0];
        out[row*2 + 1] = d1 + pb[1];
    }
}

// ---------------- launch ----------------
extern "C" void kernel_launch(void* const* d_in, const int* in_sizes, int n_in,
                              void* d_out, int out_size) {
    const int*   seq      = (const int*)  d_in[0];
    const void*  mask     =               d_in[1];
    const float* bppm     = (const float*)d_in[2];
    const float* emb      = (const float*)d_in[3];
    const float* pair_w   = (const float*)d_in[4];
    const float* pair_b   = (const float*)d_in[5];
    const float* relpos_w = (const float*)d_in[6];
    const float* relpos_b = (const float*)d_in[7];
    const float* ln1_s    = (const float*)d_in[8];
    const float* ln1_b    = (const float*)d_in[9];
    const float* qkv_w    = (const float*)d_in[10];
    const float* qkv_b    = (const float*)d_in[11];
    const float* out_w    = (const float*)d_in[12];
    const float* out_b    = (const float*)d_in[13];
    const float* ln2_s    = (const float*)d_in[14];
    const float* ln2_b    = (const float*)d_in[15];
    const float* ff1_w    = (const float*)d_in[16];
    const float* ff1_b    = (const float*)d_in[17];
    const float* ff2_w    = (const float*)d_in[18];
    const float* ff2_b    = (const float*)d_in[19];
    const float* proj_w   = (const float*)d_in[20];
    const float* proj_b   = (const float*)d_in[21];
    float* out = (float*)d_out;

    float *x, *h, *qkvB, *o, *ff;
    cudaGetSymbolAddress((void**)&x,    g_x);
    cudaGetSymbolAddress((void**)&h,    g_h);
    cudaGetSymbolAddress((void**)&qkvB, g_qkv);
    cudaGetSymbolAddress((void**)&o,    g_o);
    cudaGetSymbolAddress((void**)&ff,   g_ff);

    static int attr_set = 0;
    if (!attr_set) {
        cudaFuncSetAttribute(attn_mma_kernel,
                             cudaFuncAttributeMaxDynamicSharedMemorySize, SMEM_ATT_BYTES);
        attr_set = 1;
    }

    mask_reset_kernel<<<1, 1>>>();
    mask_detect_kernel<<<(NROW + 255) / 256, 256>>>((const unsigned char*)mask);
    mask_expand_kernel<<<(NROW + 255) / 256, 256>>>(mask);

    embed_kernel<<<(NROW * DDIM) / 256, 256>>>(seq, emb, x);

    dim3 gQKV(QKVN / 64, NROW / 128);
    dim3 gOUT(DDIM / 64, NROW / 128);
    dim3 gFF1(FFN  / 64, NROW / 128);
    dim3 gATT(LL / 128, HH, BB);

    for (int i = 0; i < DEPTH; i++) {
        ln_kernel<<<NROW / 8, 256>>>(x, ln1_s + i*DDIM, ln1_b + i*DDIM, h);
        gemm_bf16_kernel<0><<<gQKV, 256>>>(h, qkv_w + (size_t)i*QKVN*DDIM,
                                           qkv_b + i*QKVN, nullptr, qkvB,
                                           NROW, QKVN, DDIM);
        attn_mma_kernel<<<gATT, 256, SMEM_ATT_BYTES>>>(qkvB, bppm, pair_w, pair_b,
                                                       relpos_w, relpos_b, o);
        gemm_bf16_kernel<1><<<gOUT, 256>>>(o, out_w + (size_t)i*DDIM*DDIM,
                                           out_b + i*DDIM, x, x,
                                           NROW, DDIM, DDIM);
        ln_kernel<<<NROW / 8, 256>>>(x, ln2_s + i*DDIM, ln2_b + i*DDIM, h);
        gemm_bf16_kernel<2><<<gFF1, 256>>>(h, ff1_w + (size_t)i*FFN*DDIM,
                                           ff1_b + i*FFN, nullptr, ff,
                                           NROW, FFN, DDIM);
        gemm_bf16_kernel<1><<<gOUT, 256>>>(ff, ff2_w + (size_t)i*DDIM*FFN,
                                           ff2_b + i*DDIM, x, x,
                                           NROW, DDIM, FFN);
    }

    proj_kernel<<<NROW / 8, 256>>>(x, proj_w, proj_b, out);
}